// round 14
// baseline (speedup 1.0000x reference)
#include <cuda_runtime.h>
#include <cuda_bf16.h>
#include <math.h>
#include <stdint.h>

#define Bq 4
#define Sq 1024
#define Dq 768
#define Hq 12
#define HDq 64
#define FFq 3072
#define Mq (Bq*Sq)   // 4096
#define EPSq 1e-5f
#define SPLITK 4

// ---------------- scratch (static device globals; no allocation) ----------------
__device__ float g_h [Mq*Dq];
__device__ float g_q [Mq*Dq];
__device__ float g_k [Mq*Dq];
__device__ float g_v [Mq*Dq];
__device__ float g_at[Mq*Dq];
__device__ float g_x2[Mq*Dq];
__device__ float g_ff[Mq*FFq];
__device__ float g_part[SPLITK * Mq * Dq];

// ---------------- LayerNorm ----------------
__global__ void ln_kernel(const float* __restrict__ x,
                          const float* __restrict__ g,
                          const float* __restrict__ s,
                          float* __restrict__ out) {
    int row = blockIdx.x;
    int t = threadIdx.x;
    const float* xr = x + (size_t)row * Dq;
    float v0 = xr[t], v1 = xr[t + 256], v2 = xr[t + 512];
    float lsum = v0 + v1 + v2;
    float lsq  = v0*v0 + v1*v1 + v2*v2;

    __shared__ float rs[64], rq[64];
    for (int o = 16; o > 0; o >>= 1) {
        lsum += __shfl_down_sync(0xffffffff, lsum, o);
        lsq  += __shfl_down_sync(0xffffffff, lsq,  o);
    }
    int warp = t >> 5, lane = t & 31;
    if (lane == 0) { rs[warp] = lsum; rq[warp] = lsq; }
    __syncthreads();
    if (warp == 0) {
        float a = (lane < 8) ? rs[lane] : 0.f;
        float b = (lane < 8) ? rq[lane] : 0.f;
        for (int o = 4; o > 0; o >>= 1) {
            a += __shfl_down_sync(0xffffffff, a, o);
            b += __shfl_down_sync(0xffffffff, b, o);
        }
        if (lane == 0) { rs[0] = a; rq[0] = b; }
    }
    __syncthreads();
    float mean = rs[0] * (1.0f / Dq);
    float var  = rq[0] * (1.0f / Dq) - mean * mean;
    float inv  = rsqrtf(var + EPSq);
    float* orow = out + (size_t)row * Dq;
    orow[t]       = (v0 - mean) * inv * g[t]       + s[t];
    orow[t + 256] = (v1 - mean) * inv * g[t + 256] + s[t + 256];
    orow[t + 512] = (v2 - mean) * inv * g[t + 512] + s[t + 512];
}

// ---------------- shared PTX helpers ----------------
__device__ __forceinline__ uint32_t smem_u32(const void* p) {
    uint32_t a;
    asm("{ .reg .u64 t; cvta.to.shared.u64 t, %1; cvt.u32.u64 %0, t; }" : "=r"(a) : "l"(p));
    return a;
}
__device__ __forceinline__ void cp_async16(uint32_t saddr, const void* gptr) {
    asm volatile("cp.async.cg.shared.global [%0], [%1], 16;" :: "r"(saddr), "l"(gptr));
}
#define CP_COMMIT() asm volatile("cp.async.commit_group;" ::: "memory")
#define CP_WAIT2()  asm volatile("cp.async.wait_group 2;" ::: "memory")

__device__ __forceinline__ uint32_t f2tf32(float x) {
    uint32_t r;
    asm("cvt.rna.tf32.f32 %0, %1;" : "=r"(r) : "f"(x));
    return r;
}
__device__ __forceinline__ void mma_tf32(float c[4], const uint32_t a[4], const uint32_t b[2]) {
    asm("mma.sync.aligned.m16n8k8.row.col.f32.tf32.tf32.f32 "
        "{%0,%1,%2,%3}, {%4,%5,%6,%7}, {%8,%9}, {%0,%1,%2,%3};"
        : "+f"(c[0]), "+f"(c[1]), "+f"(c[2]), "+f"(c[3])
        : "r"(a[0]), "r"(a[1]), "r"(a[2]), "r"(a[3]), "r"(b[0]), "r"(b[1]));
}

// ---------------- tf32 GEMM: CTA 128x128, 512 threads, warp 32x32, 4-stage cp.async --------
// Inner loop j-jammed: small live operand set lets ptxas software-pipeline
// LDS(j+1) under mma(j) within the 64-register budget.
#define GST 20
#define STAGES 4
#define BUFO (128 * GST)                        // uint32 per operand stage
#define GSMEM_BYTES (STAGES * BUFO * 4 * 2)     // 81920 B

template<bool HAS_BIAS, bool DO_GELU, bool HAS_RES>
__device__ __forceinline__ void gemm_body(
        const float* __restrict__ A,
        const float* __restrict__ W,
        const float* __restrict__ bias,
        const float* __restrict__ res,
        float* __restrict__ C,
        int N, int K, int lda, int bm, int bn,
        uint32_t* As, uint32_t* Bs)
{
    int tid = threadIdx.x;                 // 512
    int warp = tid >> 5, lane = tid & 31;
    int wm = warp >> 2, wn = warp & 3;     // 4 x 4 warp grid, warp tile 32x32
    int gid = lane >> 2, tig = lane & 3;

    // loaders: 128 rows x 16 k per operand; 4 threads/row, 1 cp.async16 each
    int lr = tid >> 2, sel = (tid & 3) * 4;
    const float* Ap = A + (size_t)(bm * 128 + lr) * lda + sel;
    const float* Wp = W + (size_t)(bn * 128 + lr) * lda + sel;
    uint32_t sA = smem_u32(As) + (uint32_t)(lr * GST + sel) * 4u;
    uint32_t sB = smem_u32(Bs) + (uint32_t)(lr * GST + sel) * 4u;

    float c[2][4][4];
    #pragma unroll
    for (int i = 0; i < 2; i++)
        #pragma unroll
        for (int j = 0; j < 4; j++)
            #pragma unroll
            for (int f = 0; f < 4; f++) c[i][j][f] = 0.f;

    const int NT = K / 16;

    #pragma unroll
    for (int s = 0; s < STAGES - 1; s++) {
        if (s < NT) {
            cp_async16(sA + (uint32_t)(s * BUFO) * 4u, Ap + s * 16);
            cp_async16(sB + (uint32_t)(s * BUFO) * 4u, Wp + s * 16);
        }
        CP_COMMIT();
    }

    for (int t = 0; t < NT; t++) {
        CP_WAIT2();
        __syncthreads();

        int st = t & (STAGES - 1);
        const uint32_t* Ab = As + st * BUFO;
        const uint32_t* Bb = Bs + st * BUFO;

        // issue next-stage loads first (independent of this tile's math)
        int nt = t + STAGES - 1;
        if (nt < NT) {
            int ns = nt & (STAGES - 1);
            cp_async16(sA + (uint32_t)(ns * BUFO) * 4u, Ap + nt * 16);
            cp_async16(sB + (uint32_t)(ns * BUFO) * 4u, Wp + nt * 16);
        }
        CP_COMMIT();

        #pragma unroll
        for (int ks = 0; ks < 2; ks++) {
            int kb = ks * 8;
            uint32_t af[2][4];
            #pragma unroll
            for (int i = 0; i < 2; i++) {
                int row = wm * 32 + i * 16 + gid;
                af[i][0] = Ab[row * GST + kb + tig];
                af[i][1] = Ab[(row + 8) * GST + kb + tig];
                af[i][2] = Ab[row * GST + kb + tig + 4];
                af[i][3] = Ab[(row + 8) * GST + kb + tig + 4];
            }
            // j-jammed: load one B frag, fire its 2 mmas, move on
            #pragma unroll
            for (int j = 0; j < 4; j++) {
                uint32_t bf[2];
                int col = wn * 32 + j * 8 + gid;
                bf[0] = Bb[col * GST + kb + tig];
                bf[1] = Bb[col * GST + kb + tig + 4];
                mma_tf32(c[0][j], af[0], bf);
                mma_tf32(c[1][j], af[1], bf);
            }
        }
    }

    #pragma unroll
    for (int i = 0; i < 2; i++) {
        #pragma unroll
        for (int j = 0; j < 4; j++) {
            int row0 = bm * 128 + wm * 32 + i * 16 + gid;
            int col0 = bn * 128 + wn * 32 + j * 8 + 2 * tig;
            #pragma unroll
            for (int half = 0; half < 2; half++) {
                int m = row0 + half * 8;
                float v0 = c[i][j][half * 2 + 0];
                float v1 = c[i][j][half * 2 + 1];
                if (HAS_BIAS) { v0 += bias[col0]; v1 += bias[col0 + 1]; }
                if (DO_GELU) {
                    float x3 = v0 * v0 * v0;
                    float tt = tanhf(0.7978845608028654f * (v0 + 0.044715f * x3));
                    v0 = 0.5f * v0 * (1.0f + tt);
                    x3 = v1 * v1 * v1;
                    tt = tanhf(0.7978845608028654f * (v1 + 0.044715f * x3));
                    v1 = 0.5f * v1 * (1.0f + tt);
                }
                if (HAS_RES) {
                    float2 r = *(const float2*)(res + (size_t)m * N + col0);
                    v0 += r.x; v1 += r.y;
                }
                *(float2*)(C + (size_t)m * N + col0) = make_float2(v0, v1);
            }
        }
    }
}

template<bool HAS_BIAS, bool DO_GELU, bool HAS_RES>
__global__ __launch_bounds__(512, 2) void tgemm_kernel(
        const float* __restrict__ A, const float* __restrict__ W,
        const float* __restrict__ bias, const float* __restrict__ res,
        float* __restrict__ C, int N, int K, int lda) {
    extern __shared__ uint32_t smg[];
    gemm_body<HAS_BIAS, DO_GELU, HAS_RES>(A, W, bias, res, C, N, K, lda,
                                          blockIdx.y, blockIdx.x,
                                          smg, smg + STAGES * BUFO);
}

__global__ __launch_bounds__(512, 2) void qkv_kernel(
        const float* __restrict__ A,
        const float* __restrict__ Wqp, const float* __restrict__ Wkp, const float* __restrict__ Wvp,
        float* __restrict__ Qo, float* __restrict__ Ko, float* __restrict__ Vo) {
    extern __shared__ uint32_t smg[];
    const float* W = (blockIdx.z == 0) ? Wqp : (blockIdx.z == 1) ? Wkp : Wvp;
    float* C = (blockIdx.z == 0) ? Qo : (blockIdx.z == 1) ? Ko : Vo;
    gemm_body<false, false, false>(A, W, nullptr, nullptr, C, Dq, Dq, Dq,
                                   blockIdx.y, blockIdx.x,
                                   smg, smg + STAGES * BUFO);
}

__global__ __launch_bounds__(512, 2) void w2_partial_kernel(
        const float* __restrict__ A, const float* __restrict__ W,
        float* __restrict__ P) {
    extern __shared__ uint32_t smg[];
    int z = blockIdx.z;
    const int KC = FFq / SPLITK;
    gemm_body<false, false, false>(A + z * KC, W + z * KC, nullptr, nullptr,
                                   P + (size_t)z * Mq * Dq, Dq, KC, FFq,
                                   blockIdx.y, blockIdx.x,
                                   smg, smg + STAGES * BUFO);
}

__global__ __launch_bounds__(256) void w2_reduce_kernel(
        const float* __restrict__ P, const float* __restrict__ b2,
        const float* __restrict__ res, float* __restrict__ out) {
    size_t i4 = ((size_t)blockIdx.x * 256 + threadIdx.x) * 4;
    const size_t STR = (size_t)Mq * Dq;
    float4 v0 = *(const float4*)(P + i4);
    float4 v1 = *(const float4*)(P + STR + i4);
    float4 v2 = *(const float4*)(P + 2 * STR + i4);
    float4 v3 = *(const float4*)(P + 3 * STR + i4);
    int col = (int)(i4 % Dq);
    float4 bv = *(const float4*)(b2 + col);
    float4 rv = *(const float4*)(res + i4);
    float4 o;
    o.x = ((v0.x + v1.x) + (v2.x + v3.x)) + bv.x + rv.x;
    o.y = ((v0.y + v1.y) + (v2.y + v3.y)) + bv.y + rv.y;
    o.z = ((v0.z + v1.z) + (v2.z + v3.z)) + bv.z + rv.z;
    o.w = ((v0.w + v1.w) + (v2.w + v3.w)) + bv.w + rv.w;
    *(float4*)(out + i4) = o;
}

// ---------------- Flash attention on tensor cores (tf32 rna) ----------------
#define ATS 68
#define AT_SMEM_BYTES (4 * 64 * ATS * 4 + 4 * 64 * 4)

__global__ __launch_bounds__(256) void attn_kernel(const float* __restrict__ Q,
                                                   const float* __restrict__ K,
                                                   const float* __restrict__ V,
                                                   float* __restrict__ out) {
    extern __shared__ uint32_t asmem[];
    uint32_t* Qs = asmem;
    uint32_t* Ks = asmem + 64 * ATS;
    uint32_t* VT = asmem + 2 * 64 * ATS;
    uint32_t* Ps = asmem + 3 * 64 * ATS;
    float* red = (float*)(asmem + 4 * 64 * ATS);   // [4][64]

    int bh = blockIdx.y;
    int qt = 15 - blockIdx.x;
    int tid = threadIdx.x;
    int warp = tid >> 5, lane = tid & 31;
    int wm = warp >> 2, wn = warp & 3;     // 2 x 4
    int gid = lane >> 2, tig = lane & 3;

    const float* Qp = Q + (size_t)bh * Sq * HDq;
    const float* Kp = K + (size_t)bh * Sq * HDq;
    const float* Vp = V + (size_t)bh * Sq * HDq;

    for (int t = tid; t < 1024; t += 256) {
        int r = t >> 4, cc = (t & 15) * 4;
        float4 qv = *(const float4*)(Qp + (size_t)(qt * 64 + r) * HDq + cc);
        Qs[r * ATS + cc + 0] = f2tf32(qv.x * 0.015625f);
        Qs[r * ATS + cc + 1] = f2tf32(qv.y * 0.015625f);
        Qs[r * ATS + cc + 2] = f2tf32(qv.z * 0.015625f);
        Qs[r * ATS + cc + 3] = f2tf32(qv.w * 0.015625f);
    }

    float o_[2][2][4];
    float m_i[4], l_i[4];
    #pragma unroll
    for (int r = 0; r < 4; r++) { m_i[r] = -1e30f; l_i[r] = 0.f; }
    #pragma unroll
    for (int i = 0; i < 2; i++)
        #pragma unroll
        for (int j = 0; j < 2; j++)
            #pragma unroll
            for (int e = 0; e < 4; e++) o_[i][j][e] = 0.f;

    for (int kt = 0; kt <= qt; kt++) {
        __syncthreads();
        for (int t = tid; t < 1024; t += 256) {
            int k = t & 63, cc = (t >> 6) * 4;
            float4 kv = *(const float4*)(Kp + (size_t)(kt * 64 + k) * HDq + cc);
            Ks[k * ATS + cc + 0] = f2tf32(kv.x);
            Ks[k * ATS + cc + 1] = f2tf32(kv.y);
            Ks[k * ATS + cc + 2] = f2tf32(kv.z);
            Ks[k * ATS + cc + 3] = f2tf32(kv.w);
            float4 vv = *(const float4*)(Vp + (size_t)(kt * 64 + k) * HDq + cc);
            VT[(cc + 0) * ATS + k] = f2tf32(vv.x);
            VT[(cc + 1) * ATS + k] = f2tf32(vv.y);
            VT[(cc + 2) * ATS + k] = f2tf32(vv.z);
            VT[(cc + 3) * ATS + k] = f2tf32(vv.w);
        }
        __syncthreads();

        float s_[2][2][4];
        #pragma unroll
        for (int i = 0; i < 2; i++)
            #pragma unroll
            for (int j = 0; j < 2; j++)
                #pragma unroll
                for (int e = 0; e < 4; e++) s_[i][j][e] = 0.f;
        #pragma unroll
        for (int kd = 0; kd < 8; kd++) {
            int kb = kd * 8;
            uint32_t af[2][4], bf[2][2];
            #pragma unroll
            for (int i = 0; i < 2; i++) {
                int row = wm * 32 + i * 16 + gid;
                af[i][0] = Qs[row * ATS + kb + tig];
                af[i][1] = Qs[(row + 8) * ATS + kb + tig];
                af[i][2] = Qs[row * ATS + kb + tig + 4];
                af[i][3] = Qs[(row + 8) * ATS + kb + tig + 4];
            }
            #pragma unroll
            for (int j = 0; j < 2; j++) {
                int col = wn * 16 + j * 8 + gid;
                bf[j][0] = Ks[col * ATS + kb + tig];
                bf[j][1] = Ks[col * ATS + kb + tig + 4];
            }
            #pragma unroll
            for (int i = 0; i < 2; i++)
                #pragma unroll
                for (int j = 0; j < 2; j++)
                    mma_tf32(s_[i][j], af[i], bf[j]);
        }

        if (kt == qt) {
            #pragma unroll
            for (int i = 0; i < 2; i++)
                #pragma unroll
                for (int j = 0; j < 2; j++)
                    #pragma unroll
                    for (int e = 0; e < 4; e++) {
                        int row = wm * 32 + i * 16 + ((e >> 1) ? 8 : 0) + gid;
                        int col = wn * 16 + j * 8 + 2 * tig + (e & 1);
                        if (col > row) s_[i][j][e] = -1e30f;
                    }
        }

        #pragma unroll
        for (int r = 0; r < 4; r++) {
            int i = r >> 1, half = r & 1;
            float v = fmaxf(fmaxf(s_[i][0][half * 2], s_[i][0][half * 2 + 1]),
                            fmaxf(s_[i][1][half * 2], s_[i][1][half * 2 + 1]));
            v = fmaxf(v, __shfl_xor_sync(0xffffffff, v, 1));
            v = fmaxf(v, __shfl_xor_sync(0xffffffff, v, 2));
            if (tig == 0)
                red[wn * 64 + wm * 32 + i * 16 + half * 8 + gid] = v;
        }
        __syncthreads();

        float alpha[4];
        #pragma unroll
        for (int r = 0; r < 4; r++) {
            int i = r >> 1, half = r & 1;
            int rowg = wm * 32 + i * 16 + half * 8 + gid;
            float tm = fmaxf(fmaxf(red[rowg], red[64 + rowg]),
                             fmaxf(red[128 + rowg], red[192 + rowg]));
            float Mnew = fmaxf(m_i[r], tm);
            alpha[r] = __expf(m_i[r] - Mnew);
            m_i[r] = Mnew;
            l_i[r] *= alpha[r];
        }

        #pragma unroll
        for (int i = 0; i < 2; i++)
            #pragma unroll
            for (int half = 0; half < 2; half++) {
                int r = i * 2 + half;
                int row = wm * 32 + i * 16 + half * 8 + gid;
                #pragma unroll
                for (int j = 0; j < 2; j++) {
                    #pragma unroll
                    for (int e2 = 0; e2 < 2; e2++) {
                        int e = half * 2 + e2;
                        o_[i][j][e] *= alpha[r];
                        float p = __expf(s_[i][j][e] - m_i[r]);
                        l_i[r] += p;
                        int col = wn * 16 + j * 8 + 2 * tig + e2;
                        Ps[row * ATS + col] = f2tf32(p);
                    }
                }
            }
        __syncthreads();

        #pragma unroll
        for (int kk = 0; kk < 8; kk++) {
            int kb = kk * 8;
            uint32_t af[2][4], bf[2][2];
            #pragma unroll
            for (int i = 0; i < 2; i++) {
                int row = wm * 32 + i * 16 + gid;
                af[i][0] = Ps[row * ATS + kb + tig];
                af[i][1] = Ps[(row + 8) * ATS + kb + tig];
                af[i][2] = Ps[row * ATS + kb + tig + 4];
                af[i][3] = Ps[(row + 8) * ATS + kb + tig + 4];
            }
            #pragma unroll
            for (int j = 0; j < 2; j++) {
                int col = wn * 16 + j * 8 + gid;
                bf[j][0] = VT[col * ATS + kb + tig];
                bf[j][1] = VT[col * ATS + kb + tig + 4];
            }
            #pragma unroll
            for (int i = 0; i < 2; i++)
                #pragma unroll
                for (int j = 0; j < 2; j++)
                    mma_tf32(o_[i][j], af[i], bf[j]);
        }
    }

    #pragma unroll
    for (int r = 0; r < 4; r++) {
        float v = l_i[r];
        v += __shfl_xor_sync(0xffffffff, v, 1);
        v += __shfl_xor_sync(0xffffffff, v, 2);
        l_i[r] = v;
    }
    __syncthreads();
    if (tig == 0) {
        #pragma unroll
        for (int r = 0; r < 4; r++)
            red[wn * 64 + wm * 32 + (r >> 1) * 16 + (r & 1) * 8 + gid] = l_i[r];
    }
    __syncthreads();

    int b = bh / Hq, h = bh % Hq;
    #pragma unroll
    for (int i = 0; i < 2; i++)
        #pragma unroll
        for (int half = 0; half < 2; half++) {
            int rowg = wm * 32 + i * 16 + half * 8 + gid;
            float lt = ((red[rowg] + red[64 + rowg]) + (red[128 + rowg] + red[192 + rowg]));
            float inv = 1.0f / lt;
            int qrow = qt * 64 + rowg;
            #pragma unroll
            for (int j = 0; j < 2; j++) {
                int col = h * HDq + wn * 16 + j * 8 + 2 * tig;
                float v0 = o_[i][j][half * 2 + 0] * inv;
                float v1 = o_[i][j][half * 2 + 1] * inv;
                *(float2*)(out + ((size_t)(b * Sq + qrow)) * Dq + col) = make_float2(v0, v1);
            }
        }
}

// ---------------- launch ----------------
extern "C" void kernel_launch(void* const* d_in, const int* in_sizes, int n_in,
                              void* d_out, int out_size) {
    const float* x  = (const float*)d_in[0];
    const float* Wq = (const float*)d_in[1];
    const float* Wk = (const float*)d_in[2];
    const float* Wv = (const float*)d_in[3];
    const float* Wo = (const float*)d_in[4];
    const float* W1 = (const float*)d_in[5];
    const float* b1 = (const float*)d_in[6];
    const float* W2 = (const float*)d_in[7];
    const float* b2 = (const float*)d_in[8];
    const float* g1 = (const float*)d_in[9];
    const float* s1 = (const float*)d_in[10];
    const float* g2 = (const float*)d_in[11];
    const float* s2 = (const float*)d_in[12];
    float* out = (float*)d_out;

    float *h, *q, *k, *v, *at, *x2, *ff, *part;
    cudaGetSymbolAddress((void**)&h,  g_h);
    cudaGetSymbolAddress((void**)&q,  g_q);
    cudaGetSymbolAddress((void**)&k,  g_k);
    cudaGetSymbolAddress((void**)&v,  g_v);
    cudaGetSymbolAddress((void**)&at, g_at);
    cudaGetSymbolAddress((void**)&x2, g_x2);
    cudaGetSymbolAddress((void**)&ff, g_ff);
    cudaGetSymbolAddress((void**)&part, g_part);

    static bool attr_set = false;
    if (!attr_set) {
        cudaFuncSetAttribute(attn_kernel,
                             cudaFuncAttributeMaxDynamicSharedMemorySize, AT_SMEM_BYTES);
        cudaFuncSetAttribute(tgemm_kernel<false, false, true>,
                             cudaFuncAttributeMaxDynamicSharedMemorySize, GSMEM_BYTES);
        cudaFuncSetAttribute(tgemm_kernel<true, true, false>,
                             cudaFuncAttributeMaxDynamicSharedMemorySize, GSMEM_BYTES);
        cudaFuncSetAttribute(qkv_kernel,
                             cudaFuncAttributeMaxDynamicSharedMemorySize, GSMEM_BYTES);
        cudaFuncSetAttribute(w2_partial_kernel,
                             cudaFuncAttributeMaxDynamicSharedMemorySize, GSMEM_BYTES);
        attr_set = true;
    }

    dim3 gDD(Dq / 128, Mq / 128);        // (6, 32)
    dim3 gQKV(Dq / 128, Mq / 128, 3);    // (6, 32, 3)
    dim3 gDF(FFq / 128, Mq / 128);       // (24, 32)
    dim3 gW2(Dq / 128, Mq / 128, SPLITK);// (6, 32, 4)

    // LN1
    ln_kernel<<<Mq, 256>>>(x, g1, s1, h);
    // fused Q,K,V projections
    qkv_kernel<<<gQKV, 512, GSMEM_BYTES>>>(h, Wq, Wk, Wv, q, k, v);
    // flash attention (tensor cores)
    {
        dim3 ga(16, Bq * Hq);
        attn_kernel<<<ga, 256, AT_SMEM_BYTES>>>(q, k, v, at);
    }
    // output projection + residual
    tgemm_kernel<false, false, true><<<gDD, 512, GSMEM_BYTES>>>(at, Wo, nullptr, x, x2, Dq, Dq, Dq);
    // LN2
    ln_kernel<<<Mq, 256>>>(x2, g2, s2, h);
    // MLP up + GELU
    tgemm_kernel<true, true, false><<<gDF, 512, GSMEM_BYTES>>>(h, W1, b1, nullptr, ff, FFq, Dq, Dq);
    // MLP down: split-K partials + deterministic reduce
    w2_partial_kernel<<<gW2, 512, GSMEM_BYTES>>>(ff, W2, part);
    w2_reduce_kernel<<<(Mq * Dq) / (256 * 4), 256>>>(part, b2, x2, out);
}

// round 15
// speedup vs baseline: 1.0457x; 1.0457x over previous
#include <cuda_runtime.h>
#include <cuda_bf16.h>
#include <math.h>
#include <stdint.h>

#define Bq 4
#define Sq 1024
#define Dq 768
#define Hq 12
#define HDq 64
#define FFq 3072
#define Mq (Bq*Sq)   // 4096
#define EPSq 1e-5f
#define SPLITK 4

// ---------------- scratch (static device globals; no allocation) ----------------
__device__ float g_h [Mq*Dq];
__device__ float g_q [Mq*Dq];
__device__ float g_k [Mq*Dq];
__device__ float g_v [Mq*Dq];
__device__ float g_at[Mq*Dq];
__device__ float g_x2[Mq*Dq];
__device__ float g_ff[Mq*FFq];
__device__ float g_part[SPLITK * Mq * Dq];

// ---------------- LayerNorm ----------------
__global__ void ln_kernel(const float* __restrict__ x,
                          const float* __restrict__ g,
                          const float* __restrict__ s,
                          float* __restrict__ out) {
    int row = blockIdx.x;
    int t = threadIdx.x;
    const float* xr = x + (size_t)row * Dq;
    float v0 = xr[t], v1 = xr[t + 256], v2 = xr[t + 512];
    float lsum = v0 + v1 + v2;
    float lsq  = v0*v0 + v1*v1 + v2*v2;

    __shared__ float rs[64], rq[64];
    for (int o = 16; o > 0; o >>= 1) {
        lsum += __shfl_down_sync(0xffffffff, lsum, o);
        lsq  += __shfl_down_sync(0xffffffff, lsq,  o);
    }
    int warp = t >> 5, lane = t & 31;
    if (lane == 0) { rs[warp] = lsum; rq[warp] = lsq; }
    __syncthreads();
    if (warp == 0) {
        float a = (lane < 8) ? rs[lane] : 0.f;
        float b = (lane < 8) ? rq[lane] : 0.f;
        for (int o = 4; o > 0; o >>= 1) {
            a += __shfl_down_sync(0xffffffff, a, o);
            b += __shfl_down_sync(0xffffffff, b, o);
        }
        if (lane == 0) { rs[0] = a; rq[0] = b; }
    }
    __syncthreads();
    float mean = rs[0] * (1.0f / Dq);
    float var  = rq[0] * (1.0f / Dq) - mean * mean;
    float inv  = rsqrtf(var + EPSq);
    float* orow = out + (size_t)row * Dq;
    orow[t]       = (v0 - mean) * inv * g[t]       + s[t];
    orow[t + 256] = (v1 - mean) * inv * g[t + 256] + s[t + 256];
    orow[t + 512] = (v2 - mean) * inv * g[t + 512] + s[t + 512];
}

// ---------------- shared PTX helpers ----------------
__device__ __forceinline__ uint32_t smem_u32(const void* p) {
    uint32_t a;
    asm("{ .reg .u64 t; cvta.to.shared.u64 t, %1; cvt.u32.u64 %0, t; }" : "=r"(a) : "l"(p));
    return a;
}
__device__ __forceinline__ void cp_async16(uint32_t saddr, const void* gptr) {
    asm volatile("cp.async.cg.shared.global [%0], [%1], 16;" :: "r"(saddr), "l"(gptr));
}
#define CP_COMMIT() asm volatile("cp.async.commit_group;" ::: "memory")
#define CP_WAIT3()  asm volatile("cp.async.wait_group 3;" ::: "memory")

__device__ __forceinline__ uint32_t f2tf32(float x) {
    uint32_t r;
    asm("cvt.rna.tf32.f32 %0, %1;" : "=r"(r) : "f"(x));
    return r;
}
__device__ __forceinline__ void mma_tf32(float c[4], const uint32_t a[4], const uint32_t b[2]) {
    asm("mma.sync.aligned.m16n8k8.row.col.f32.tf32.tf32.f32 "
        "{%0,%1,%2,%3}, {%4,%5,%6,%7}, {%8,%9}, {%0,%1,%2,%3};"
        : "+f"(c[0]), "+f"(c[1]), "+f"(c[2]), "+f"(c[3])
        : "r"(a[0]), "r"(a[1]), "r"(a[2]), "r"(a[3]), "r"(b[0]), "r"(b[1]));
}

// ---------------- tf32 GEMM: CTA 128x128, 512 threads, warp 32x32, 5-stage cp.async --------
#define GST 20
#define STAGES 5
#define BUFO (128 * GST)                        // uint32 per operand stage (10240 B)
#define GSMEM_BYTES (STAGES * BUFO * 4 * 2)     // 102400 B

template<bool HAS_BIAS, bool DO_GELU, bool HAS_RES>
__device__ __forceinline__ void gemm_body(
        const float* __restrict__ A,
        const float* __restrict__ W,
        const float* __restrict__ bias,
        const float* __restrict__ res,
        float* __restrict__ C,
        int N, int K, int lda, int bm, int bn,
        uint32_t* As, uint32_t* Bs)
{
    int tid = threadIdx.x;                 // 512
    int warp = tid >> 5, lane = tid & 31;
    int wm = warp >> 2, wn = warp & 3;     // 4 x 4 warp grid, warp tile 32x32
    int gid = lane >> 2, tig = lane & 3;

    // loaders: 128 rows x 16 k per operand; 4 threads/row, 1 cp.async16 each
    int lr = tid >> 2, sel = (tid & 3) * 4;
    const float* Ap = A + (size_t)(bm * 128 + lr) * lda + sel;
    const float* Wp = W + (size_t)(bn * 128 + lr) * lda + sel;
    uint32_t sA = smem_u32(As) + (uint32_t)(lr * GST + sel) * 4u;
    uint32_t sB = smem_u32(Bs) + (uint32_t)(lr * GST + sel) * 4u;

    float c[2][4][4];
    #pragma unroll
    for (int i = 0; i < 2; i++)
        #pragma unroll
        for (int j = 0; j < 4; j++)
            #pragma unroll
            for (int f = 0; f < 4; f++) c[i][j][f] = 0.f;

    const int NT = K / 16;

    #pragma unroll
    for (int s = 0; s < STAGES - 1; s++) {
        if (s < NT) {
            cp_async16(sA + (uint32_t)(s * BUFO) * 4u, Ap + s * 16);
            cp_async16(sB + (uint32_t)(s * BUFO) * 4u, Wp + s * 16);
        }
        CP_COMMIT();
    }

    int st = 0;
    for (int t = 0; t < NT; t++) {
        CP_WAIT3();
        __syncthreads();

        const uint32_t* Ab = As + st * BUFO;
        const uint32_t* Bb = Bs + st * BUFO;
        #pragma unroll
        for (int ks = 0; ks < 2; ks++) {
            int kb = ks * 8;
            uint32_t af[2][4], bf[4][2];
            #pragma unroll
            for (int i = 0; i < 2; i++) {
                int row = wm * 32 + i * 16 + gid;
                af[i][0] = Ab[row * GST + kb + tig];
                af[i][1] = Ab[(row + 8) * GST + kb + tig];
                af[i][2] = Ab[row * GST + kb + tig + 4];
                af[i][3] = Ab[(row + 8) * GST + kb + tig + 4];
            }
            #pragma unroll
            for (int j = 0; j < 4; j++) {
                int col = wn * 32 + j * 8 + gid;
                bf[j][0] = Bb[col * GST + kb + tig];
                bf[j][1] = Bb[col * GST + kb + tig + 4];
            }
            #pragma unroll
            for (int i = 0; i < 2; i++)
                #pragma unroll
                for (int j = 0; j < 4; j++)
                    mma_tf32(c[i][j], af[i], bf[j]);
        }

        int nt = t + STAGES - 1;
        if (nt < NT) {
            int ns = st + (STAGES - 1); if (ns >= STAGES) ns -= STAGES;
            cp_async16(sA + (uint32_t)(ns * BUFO) * 4u, Ap + nt * 16);
            cp_async16(sB + (uint32_t)(ns * BUFO) * 4u, Wp + nt * 16);
        }
        CP_COMMIT();
        if (++st == STAGES) st = 0;
    }

    #pragma unroll
    for (int i = 0; i < 2; i++) {
        #pragma unroll
        for (int j = 0; j < 4; j++) {
            int row0 = bm * 128 + wm * 32 + i * 16 + gid;
            int col0 = bn * 128 + wn * 32 + j * 8 + 2 * tig;
            #pragma unroll
            for (int half = 0; half < 2; half++) {
                int m = row0 + half * 8;
                float v0 = c[i][j][half * 2 + 0];
                float v1 = c[i][j][half * 2 + 1];
                if (HAS_BIAS) { v0 += bias[col0]; v1 += bias[col0 + 1]; }
                if (DO_GELU) {
                    float x3 = v0 * v0 * v0;
                    float tt = tanhf(0.7978845608028654f * (v0 + 0.044715f * x3));
                    v0 = 0.5f * v0 * (1.0f + tt);
                    x3 = v1 * v1 * v1;
                    tt = tanhf(0.7978845608028654f * (v1 + 0.044715f * x3));
                    v1 = 0.5f * v1 * (1.0f + tt);
                }
                if (HAS_RES) {
                    float2 r = *(const float2*)(res + (size_t)m * N + col0);
                    v0 += r.x; v1 += r.y;
                }
                *(float2*)(C + (size_t)m * N + col0) = make_float2(v0, v1);
            }
        }
    }
}

template<bool HAS_BIAS, bool DO_GELU, bool HAS_RES>
__global__ __launch_bounds__(512, 2) void tgemm_kernel(
        const float* __restrict__ A, const float* __restrict__ W,
        const float* __restrict__ bias, const float* __restrict__ res,
        float* __restrict__ C, int N, int K, int lda) {
    extern __shared__ uint32_t smg[];
    gemm_body<HAS_BIAS, DO_GELU, HAS_RES>(A, W, bias, res, C, N, K, lda,
                                          blockIdx.y, blockIdx.x,
                                          smg, smg + STAGES * BUFO);
}

__global__ __launch_bounds__(512, 2) void qkv_kernel(
        const float* __restrict__ A,
        const float* __restrict__ Wqp, const float* __restrict__ Wkp, const float* __restrict__ Wvp,
        float* __restrict__ Qo, float* __restrict__ Ko, float* __restrict__ Vo) {
    extern __shared__ uint32_t smg[];
    const float* W = (blockIdx.z == 0) ? Wqp : (blockIdx.z == 1) ? Wkp : Wvp;
    float* C = (blockIdx.z == 0) ? Qo : (blockIdx.z == 1) ? Ko : Vo;
    gemm_body<false, false, false>(A, W, nullptr, nullptr, C, Dq, Dq, Dq,
                                   blockIdx.y, blockIdx.x,
                                   smg, smg + STAGES * BUFO);
}

__global__ __launch_bounds__(512, 2) void w2_partial_kernel(
        const float* __restrict__ A, const float* __restrict__ W,
        float* __restrict__ P) {
    extern __shared__ uint32_t smg[];
    int z = blockIdx.z;
    const int KC = FFq / SPLITK;
    gemm_body<false, false, false>(A + z * KC, W + z * KC, nullptr, nullptr,
                                   P + (size_t)z * Mq * Dq, Dq, KC, FFq,
                                   blockIdx.y, blockIdx.x,
                                   smg, smg + STAGES * BUFO);
}

__global__ __launch_bounds__(256) void w2_reduce_kernel(
        const float* __restrict__ P, const float* __restrict__ b2,
        const float* __restrict__ res, float* __restrict__ out) {
    size_t i4 = ((size_t)blockIdx.x * 256 + threadIdx.x) * 4;
    const size_t STR = (size_t)Mq * Dq;
    float4 v0 = *(const float4*)(P + i4);
    float4 v1 = *(const float4*)(P + STR + i4);
    float4 v2 = *(const float4*)(P + 2 * STR + i4);
    float4 v3 = *(const float4*)(P + 3 * STR + i4);
    int col = (int)(i4 % Dq);
    float4 bv = *(const float4*)(b2 + col);
    float4 rv = *(const float4*)(res + i4);
    float4 o;
    o.x = ((v0.x + v1.x) + (v2.x + v3.x)) + bv.x + rv.x;
    o.y = ((v0.y + v1.y) + (v2.y + v3.y)) + bv.y + rv.y;
    o.z = ((v0.z + v1.z) + (v2.z + v3.z)) + bv.z + rv.z;
    o.w = ((v0.w + v1.w) + (v2.w + v3.w)) + bv.w + rv.w;
    *(float4*)(out + i4) = o;
}

// ---------------- Flash attention on tensor cores (tf32 rna) ----------------
#define ATS 68
#define AT_SMEM_BYTES (4 * 64 * ATS * 4 + 4 * 64 * 4)

__global__ __launch_bounds__(256) void attn_kernel(const float* __restrict__ Q,
                                                   const float* __restrict__ K,
                                                   const float* __restrict__ V,
                                                   float* __restrict__ out) {
    extern __shared__ uint32_t asmem[];
    uint32_t* Qs = asmem;
    uint32_t* Ks = asmem + 64 * ATS;
    uint32_t* VT = asmem + 2 * 64 * ATS;
    uint32_t* Ps = asmem + 3 * 64 * ATS;
    float* red = (float*)(asmem + 4 * 64 * ATS);   // [4][64]

    int bh = blockIdx.y;
    int qt = 15 - blockIdx.x;
    int tid = threadIdx.x;
    int warp = tid >> 5, lane = tid & 31;
    int wm = warp >> 2, wn = warp & 3;     // 2 x 4
    int gid = lane >> 2, tig = lane & 3;

    const float* Qp = Q + (size_t)bh * Sq * HDq;
    const float* Kp = K + (size_t)bh * Sq * HDq;
    const float* Vp = V + (size_t)bh * Sq * HDq;

    for (int t = tid; t < 1024; t += 256) {
        int r = t >> 4, cc = (t & 15) * 4;
        float4 qv = *(const float4*)(Qp + (size_t)(qt * 64 + r) * HDq + cc);
        Qs[r * ATS + cc + 0] = f2tf32(qv.x * 0.015625f);
        Qs[r * ATS + cc + 1] = f2tf32(qv.y * 0.015625f);
        Qs[r * ATS + cc + 2] = f2tf32(qv.z * 0.015625f);
        Qs[r * ATS + cc + 3] = f2tf32(qv.w * 0.015625f);
    }

    float o_[2][2][4];
    float m_i[4], l_i[4];
    #pragma unroll
    for (int r = 0; r < 4; r++) { m_i[r] = -1e30f; l_i[r] = 0.f; }
    #pragma unroll
    for (int i = 0; i < 2; i++)
        #pragma unroll
        for (int j = 0; j < 2; j++)
            #pragma unroll
            for (int e = 0; e < 4; e++) o_[i][j][e] = 0.f;

    for (int kt = 0; kt <= qt; kt++) {
        __syncthreads();
        for (int t = tid; t < 1024; t += 256) {
            int k = t & 63, cc = (t >> 6) * 4;
            float4 kv = *(const float4*)(Kp + (size_t)(kt * 64 + k) * HDq + cc);
            Ks[k * ATS + cc + 0] = f2tf32(kv.x);
            Ks[k * ATS + cc + 1] = f2tf32(kv.y);
            Ks[k * ATS + cc + 2] = f2tf32(kv.z);
            Ks[k * ATS + cc + 3] = f2tf32(kv.w);
            float4 vv = *(const float4*)(Vp + (size_t)(kt * 64 + k) * HDq + cc);
            VT[(cc + 0) * ATS + k] = f2tf32(vv.x);
            VT[(cc + 1) * ATS + k] = f2tf32(vv.y);
            VT[(cc + 2) * ATS + k] = f2tf32(vv.z);
            VT[(cc + 3) * ATS + k] = f2tf32(vv.w);
        }
        __syncthreads();

        float s_[2][2][4];
        #pragma unroll
        for (int i = 0; i < 2; i++)
            #pragma unroll
            for (int j = 0; j < 2; j++)
                #pragma unroll
                for (int e = 0; e < 4; e++) s_[i][j][e] = 0.f;
        #pragma unroll
        for (int kd = 0; kd < 8; kd++) {
            int kb = kd * 8;
            uint32_t af[2][4], bf[2][2];
            #pragma unroll
            for (int i = 0; i < 2; i++) {
                int row = wm * 32 + i * 16 + gid;
                af[i][0] = Qs[row * ATS + kb + tig];
                af[i][1] = Qs[(row + 8) * ATS + kb + tig];
                af[i][2] = Qs[row * ATS + kb + tig + 4];
                af[i][3] = Qs[(row + 8) * ATS + kb + tig + 4];
            }
            #pragma unroll
            for (int j = 0; j < 2; j++) {
                int col = wn * 16 + j * 8 + gid;
                bf[j][0] = Ks[col * ATS + kb + tig];
                bf[j][1] = Ks[col * ATS + kb + tig + 4];
            }
            #pragma unroll
            for (int i = 0; i < 2; i++)
                #pragma unroll
                for (int j = 0; j < 2; j++)
                    mma_tf32(s_[i][j], af[i], bf[j]);
        }

        if (kt == qt) {
            #pragma unroll
            for (int i = 0; i < 2; i++)
                #pragma unroll
                for (int j = 0; j < 2; j++)
                    #pragma unroll
                    for (int e = 0; e < 4; e++) {
                        int row = wm * 32 + i * 16 + ((e >> 1) ? 8 : 0) + gid;
                        int col = wn * 16 + j * 8 + 2 * tig + (e & 1);
                        if (col > row) s_[i][j][e] = -1e30f;
                    }
        }

        #pragma unroll
        for (int r = 0; r < 4; r++) {
            int i = r >> 1, half = r & 1;
            float v = fmaxf(fmaxf(s_[i][0][half * 2], s_[i][0][half * 2 + 1]),
                            fmaxf(s_[i][1][half * 2], s_[i][1][half * 2 + 1]));
            v = fmaxf(v, __shfl_xor_sync(0xffffffff, v, 1));
            v = fmaxf(v, __shfl_xor_sync(0xffffffff, v, 2));
            if (tig == 0)
                red[wn * 64 + wm * 32 + i * 16 + half * 8 + gid] = v;
        }
        __syncthreads();

        float alpha[4];
        #pragma unroll
        for (int r = 0; r < 4; r++) {
            int i = r >> 1, half = r & 1;
            int rowg = wm * 32 + i * 16 + half * 8 + gid;
            float tm = fmaxf(fmaxf(red[rowg], red[64 + rowg]),
                             fmaxf(red[128 + rowg], red[192 + rowg]));
            float Mnew = fmaxf(m_i[r], tm);
            alpha[r] = __expf(m_i[r] - Mnew);
            m_i[r] = Mnew;
            l_i[r] *= alpha[r];
        }

        #pragma unroll
        for (int i = 0; i < 2; i++)
            #pragma unroll
            for (int half = 0; half < 2; half++) {
                int r = i * 2 + half;
                int row = wm * 32 + i * 16 + half * 8 + gid;
                #pragma unroll
                for (int j = 0; j < 2; j++) {
                    #pragma unroll
                    for (int e2 = 0; e2 < 2; e2++) {
                        int e = half * 2 + e2;
                        o_[i][j][e] *= alpha[r];
                        float p = __expf(s_[i][j][e] - m_i[r]);
                        l_i[r] += p;
                        int col = wn * 16 + j * 8 + 2 * tig + e2;
                        Ps[row * ATS + col] = f2tf32(p);
                    }
                }
            }
        __syncthreads();

        #pragma unroll
        for (int kk = 0; kk < 8; kk++) {
            int kb = kk * 8;
            uint32_t af[2][4], bf[2][2];
            #pragma unroll
            for (int i = 0; i < 2; i++) {
                int row = wm * 32 + i * 16 + gid;
                af[i][0] = Ps[row * ATS + kb + tig];
                af[i][1] = Ps[(row + 8) * ATS + kb + tig];
                af[i][2] = Ps[row * ATS + kb + tig + 4];
                af[i][3] = Ps[(row + 8) * ATS + kb + tig + 4];
            }
            #pragma unroll
            for (int j = 0; j < 2; j++) {
                int col = wn * 16 + j * 8 + gid;
                bf[j][0] = VT[col * ATS + kb + tig];
                bf[j][1] = VT[col * ATS + kb + tig + 4];
            }
            #pragma unroll
            for (int i = 0; i < 2; i++)
                #pragma unroll
                for (int j = 0; j < 2; j++)
                    mma_tf32(o_[i][j], af[i], bf[j]);
        }
    }

    #pragma unroll
    for (int r = 0; r < 4; r++) {
        float v = l_i[r];
        v += __shfl_xor_sync(0xffffffff, v, 1);
        v += __shfl_xor_sync(0xffffffff, v, 2);
        l_i[r] = v;
    }
    __syncthreads();
    if (tig == 0) {
        #pragma unroll
        for (int r = 0; r < 4; r++)
            red[wn * 64 + wm * 32 + (r >> 1) * 16 + (r & 1) * 8 + gid] = l_i[r];
    }
    __syncthreads();

    int b = bh / Hq, h = bh % Hq;
    #pragma unroll
    for (int i = 0; i < 2; i++)
        #pragma unroll
        for (int half = 0; half < 2; half++) {
            int rowg = wm * 32 + i * 16 + half * 8 + gid;
            float lt = ((red[rowg] + red[64 + rowg]) + (red[128 + rowg] + red[192 + rowg]));
            float inv = 1.0f / lt;
            int qrow = qt * 64 + rowg;
            #pragma unroll
            for (int j = 0; j < 2; j++) {
                int col = h * HDq + wn * 16 + j * 8 + 2 * tig;
                float v0 = o_[i][j][half * 2 + 0] * inv;
                float v1 = o_[i][j][half * 2 + 1] * inv;
                *(float2*)(out + ((size_t)(b * Sq + qrow)) * Dq + col) = make_float2(v0, v1);
            }
        }
}

// ---------------- launch ----------------
extern "C" void kernel_launch(void* const* d_in, const int* in_sizes, int n_in,
                              void* d_out, int out_size) {
    const float* x  = (const float*)d_in[0];
    const float* Wq = (const float*)d_in[1];
    const float* Wk = (const float*)d_in[2];
    const float* Wv = (const float*)d_in[3];
    const float* Wo = (const float*)d_in[4];
    const float* W1 = (const float*)d_in[5];
    const float* b1 = (const float*)d_in[6];
    const float* W2 = (const float*)d_in[7];
    const float* b2 = (const float*)d_in[8];
    const float* g1 = (const float*)d_in[9];
    const float* s1 = (const float*)d_in[10];
    const float* g2 = (const float*)d_in[11];
    const float* s2 = (const float*)d_in[12];
    float* out = (float*)d_out;

    float *h, *q, *k, *v, *at, *x2, *ff, *part;
    cudaGetSymbolAddress((void**)&h,  g_h);
    cudaGetSymbolAddress((void**)&q,  g_q);
    cudaGetSymbolAddress((void**)&k,  g_k);
    cudaGetSymbolAddress((void**)&v,  g_v);
    cudaGetSymbolAddress((void**)&at, g_at);
    cudaGetSymbolAddress((void**)&x2, g_x2);
    cudaGetSymbolAddress((void**)&ff, g_ff);
    cudaGetSymbolAddress((void**)&part, g_part);

    static bool attr_set = false;
    if (!attr_set) {
        cudaFuncSetAttribute(attn_kernel,
                             cudaFuncAttributeMaxDynamicSharedMemorySize, AT_SMEM_BYTES);
        cudaFuncSetAttribute(tgemm_kernel<false, false, true>,
                             cudaFuncAttributeMaxDynamicSharedMemorySize, GSMEM_BYTES);
        cudaFuncSetAttribute(tgemm_kernel<true, true, false>,
                             cudaFuncAttributeMaxDynamicSharedMemorySize, GSMEM_BYTES);
        cudaFuncSetAttribute(qkv_kernel,
                             cudaFuncAttributeMaxDynamicSharedMemorySize, GSMEM_BYTES);
        cudaFuncSetAttribute(w2_partial_kernel,
                             cudaFuncAttributeMaxDynamicSharedMemorySize, GSMEM_BYTES);
        attr_set = true;
    }

    dim3 gDD(Dq / 128, Mq / 128);        // (6, 32)
    dim3 gQKV(Dq / 128, Mq / 128, 3);    // (6, 32, 3)
    dim3 gDF(FFq / 128, Mq / 128);       // (24, 32)
    dim3 gW2(Dq / 128, Mq / 128, SPLITK);// (6, 32, 4)

    // LN1
    ln_kernel<<<Mq, 256>>>(x, g1, s1, h);
    // fused Q,K,V projections
    qkv_kernel<<<gQKV, 512, GSMEM_BYTES>>>(h, Wq, Wk, Wv, q, k, v);
    // flash attention (tensor cores)
    {
        dim3 ga(16, Bq * Hq);
        attn_kernel<<<ga, 256, AT_SMEM_BYTES>>>(q, k, v, at);
    }
    // output projection + residual
    tgemm_kernel<false, false, true><<<gDD, 512, GSMEM_BYTES>>>(at, Wo, nullptr, x, x2, Dq, Dq, Dq);
    // LN2
    ln_kernel<<<Mq, 256>>>(x2, g2, s2, h);
    // MLP up + GELU
    tgemm_kernel<true, true, false><<<gDF, 512, GSMEM_BYTES>>>(h, W1, b1, nullptr, ff, FFq, Dq, Dq);
    // MLP down: split-K partials + deterministic reduce
    w2_partial_kernel<<<gW2, 512, GSMEM_BYTES>>>(ff, W2, part);
    w2_reduce_kernel<<<(Mq * Dq) / (256 * 4), 256>>>(part, b2, x2, out);
}

// round 16
// speedup vs baseline: 1.0585x; 1.0122x over previous
#include <cuda_runtime.h>
#include <cuda_bf16.h>
#include <math.h>
#include <stdint.h>

#define Bq 4
#define Sq 1024
#define Dq 768
#define Hq 12
#define HDq 64
#define FFq 3072
#define Mq (Bq*Sq)   // 4096
#define EPSq 1e-5f
#define SPLITK 2

// ---------------- scratch (static device globals; no allocation) ----------------
__device__ float g_h [Mq*Dq];
__device__ float g_q [Mq*Dq];
__device__ float g_k [Mq*Dq];
__device__ float g_v [Mq*Dq];
__device__ float g_at[Mq*Dq];
__device__ float g_x2[Mq*Dq];
__device__ float g_ff[Mq*FFq];
__device__ float g_part[SPLITK * Mq * Dq];

// ---------------- LayerNorm ----------------
__global__ void ln_kernel(const float* __restrict__ x,
                          const float* __restrict__ g,
                          const float* __restrict__ s,
                          float* __restrict__ out) {
    int row = blockIdx.x;
    int t = threadIdx.x;
    const float* xr = x + (size_t)row * Dq;
    float v0 = xr[t], v1 = xr[t + 256], v2 = xr[t + 512];
    float lsum = v0 + v1 + v2;
    float lsq  = v0*v0 + v1*v1 + v2*v2;

    __shared__ float rs[64], rq[64];
    for (int o = 16; o > 0; o >>= 1) {
        lsum += __shfl_down_sync(0xffffffff, lsum, o);
        lsq  += __shfl_down_sync(0xffffffff, lsq,  o);
    }
    int warp = t >> 5, lane = t & 31;
    if (lane == 0) { rs[warp] = lsum; rq[warp] = lsq; }
    __syncthreads();
    if (warp == 0) {
        float a = (lane < 8) ? rs[lane] : 0.f;
        float b = (lane < 8) ? rq[lane] : 0.f;
        for (int o = 4; o > 0; o >>= 1) {
            a += __shfl_down_sync(0xffffffff, a, o);
            b += __shfl_down_sync(0xffffffff, b, o);
        }
        if (lane == 0) { rs[0] = a; rq[0] = b; }
    }
    __syncthreads();
    float mean = rs[0] * (1.0f / Dq);
    float var  = rq[0] * (1.0f / Dq) - mean * mean;
    float inv  = rsqrtf(var + EPSq);
    float* orow = out + (size_t)row * Dq;
    orow[t]       = (v0 - mean) * inv * g[t]       + s[t];
    orow[t + 256] = (v1 - mean) * inv * g[t + 256] + s[t + 256];
    orow[t + 512] = (v2 - mean) * inv * g[t + 512] + s[t + 512];
}

// ---------------- shared PTX helpers ----------------
__device__ __forceinline__ uint32_t smem_u32(const void* p) {
    uint32_t a;
    asm("{ .reg .u64 t; cvta.to.shared.u64 t, %1; cvt.u32.u64 %0, t; }" : "=r"(a) : "l"(p));
    return a;
}
__device__ __forceinline__ void cp_async16(uint32_t saddr, const void* gptr) {
    asm volatile("cp.async.cg.shared.global [%0], [%1], 16;" :: "r"(saddr), "l"(gptr));
}
#define CP_COMMIT() asm volatile("cp.async.commit_group;" ::: "memory")
#define CP_WAIT2()  asm volatile("cp.async.wait_group 2;" ::: "memory")

__device__ __forceinline__ uint32_t f2tf32(float x) {
    uint32_t r;
    asm("cvt.rna.tf32.f32 %0, %1;" : "=r"(r) : "f"(x));
    return r;
}
__device__ __forceinline__ void mma_tf32(float c[4], const uint32_t a[4], const uint32_t b[2]) {
    asm("mma.sync.aligned.m16n8k8.row.col.f32.tf32.tf32.f32 "
        "{%0,%1,%2,%3}, {%4,%5,%6,%7}, {%8,%9}, {%0,%1,%2,%3};"
        : "+f"(c[0]), "+f"(c[1]), "+f"(c[2]), "+f"(c[3])
        : "r"(a[0]), "r"(a[1]), "r"(a[2]), "r"(a[3]), "r"(b[0]), "r"(b[1]));
}

// ---------------- tf32 GEMM A: CTA 128x128, 512 threads, warp 32x32, 4-stage (R13) ------
#define GST 20
#define STAGES 4
#define BUFO (128 * GST)                        // uint32 per operand stage
#define GSMEM_BYTES (STAGES * BUFO * 4 * 2)     // 81920 B

template<bool HAS_BIAS, bool DO_GELU, bool HAS_RES>
__device__ __forceinline__ void gemm_body(
        const float* __restrict__ A,
        const float* __restrict__ W,
        const float* __restrict__ bias,
        const float* __restrict__ res,
        float* __restrict__ C,
        int N, int K, int lda, int bm, int bn,
        uint32_t* As, uint32_t* Bs)
{
    int tid = threadIdx.x;                 // 512
    int warp = tid >> 5, lane = tid & 31;
    int wm = warp >> 2, wn = warp & 3;     // 4 x 4 warp grid, warp tile 32x32
    int gid = lane >> 2, tig = lane & 3;

    int lr = tid >> 2, sel = (tid & 3) * 4;
    const float* Ap = A + (size_t)(bm * 128 + lr) * lda + sel;
    const float* Wp = W + (size_t)(bn * 128 + lr) * lda + sel;
    uint32_t sA = smem_u32(As) + (uint32_t)(lr * GST + sel) * 4u;
    uint32_t sB = smem_u32(Bs) + (uint32_t)(lr * GST + sel) * 4u;

    float c[2][4][4];
    #pragma unroll
    for (int i = 0; i < 2; i++)
        #pragma unroll
        for (int j = 0; j < 4; j++)
            #pragma unroll
            for (int f = 0; f < 4; f++) c[i][j][f] = 0.f;

    const int NT = K / 16;

    #pragma unroll
    for (int s = 0; s < STAGES - 1; s++) {
        if (s < NT) {
            cp_async16(sA + (uint32_t)(s * BUFO) * 4u, Ap + s * 16);
            cp_async16(sB + (uint32_t)(s * BUFO) * 4u, Wp + s * 16);
        }
        CP_COMMIT();
    }

    for (int t = 0; t < NT; t++) {
        CP_WAIT2();
        __syncthreads();

        int st = t & (STAGES - 1);
        const uint32_t* Ab = As + st * BUFO;
        const uint32_t* Bb = Bs + st * BUFO;
        #pragma unroll
        for (int ks = 0; ks < 2; ks++) {
            int kb = ks * 8;
            uint32_t af[2][4], bf[4][2];
            #pragma unroll
            for (int i = 0; i < 2; i++) {
                int row = wm * 32 + i * 16 + gid;
                af[i][0] = Ab[row * GST + kb + tig];
                af[i][1] = Ab[(row + 8) * GST + kb + tig];
                af[i][2] = Ab[row * GST + kb + tig + 4];
                af[i][3] = Ab[(row + 8) * GST + kb + tig + 4];
            }
            #pragma unroll
            for (int j = 0; j < 4; j++) {
                int col = wn * 32 + j * 8 + gid;
                bf[j][0] = Bb[col * GST + kb + tig];
                bf[j][1] = Bb[col * GST + kb + tig + 4];
            }
            #pragma unroll
            for (int i = 0; i < 2; i++)
                #pragma unroll
                for (int j = 0; j < 4; j++)
                    mma_tf32(c[i][j], af[i], bf[j]);
        }

        int nt = t + STAGES - 1;
        if (nt < NT) {
            int ns = nt & (STAGES - 1);
            cp_async16(sA + (uint32_t)(ns * BUFO) * 4u, Ap + nt * 16);
            cp_async16(sB + (uint32_t)(ns * BUFO) * 4u, Wp + nt * 16);
        }
        CP_COMMIT();
    }

    #pragma unroll
    for (int i = 0; i < 2; i++) {
        #pragma unroll
        for (int j = 0; j < 4; j++) {
            int row0 = bm * 128 + wm * 32 + i * 16 + gid;
            int col0 = bn * 128 + wn * 32 + j * 8 + 2 * tig;
            #pragma unroll
            for (int half = 0; half < 2; half++) {
                int m = row0 + half * 8;
                float v0 = c[i][j][half * 2 + 0];
                float v1 = c[i][j][half * 2 + 1];
                if (HAS_BIAS) { v0 += bias[col0]; v1 += bias[col0 + 1]; }
                if (DO_GELU) {
                    float x3 = v0 * v0 * v0;
                    float tt = tanhf(0.7978845608028654f * (v0 + 0.044715f * x3));
                    v0 = 0.5f * v0 * (1.0f + tt);
                    x3 = v1 * v1 * v1;
                    tt = tanhf(0.7978845608028654f * (v1 + 0.044715f * x3));
                    v1 = 0.5f * v1 * (1.0f + tt);
                }
                if (HAS_RES) {
                    float2 r = *(const float2*)(res + (size_t)m * N + col0);
                    v0 += r.x; v1 += r.y;
                }
                *(float2*)(C + (size_t)m * N + col0) = make_float2(v0, v1);
            }
        }
    }
}

template<bool HAS_BIAS, bool DO_GELU, bool HAS_RES>
__global__ __launch_bounds__(512, 2) void tgemm_kernel(
        const float* __restrict__ A, const float* __restrict__ W,
        const float* __restrict__ bias, const float* __restrict__ res,
        float* __restrict__ C, int N, int K, int lda) {
    extern __shared__ uint32_t smg[];
    gemm_body<HAS_BIAS, DO_GELU, HAS_RES>(A, W, bias, res, C, N, K, lda,
                                          blockIdx.y, blockIdx.x,
                                          smg, smg + STAGES * BUFO);
}

__global__ __launch_bounds__(512, 2) void qkv_kernel(
        const float* __restrict__ A,
        const float* __restrict__ Wqp, const float* __restrict__ Wkp, const float* __restrict__ Wvp,
        float* __restrict__ Qo, float* __restrict__ Ko, float* __restrict__ Vo) {
    extern __shared__ uint32_t smg[];
    const float* W = (blockIdx.z == 0) ? Wqp : (blockIdx.z == 1) ? Wkp : Wvp;
    float* C = (blockIdx.z == 0) ? Qo : (blockIdx.z == 1) ? Ko : Vo;
    gemm_body<false, false, false>(A, W, nullptr, nullptr, C, Dq, Dq, Dq,
                                   blockIdx.y, blockIdx.x,
                                   smg, smg + STAGES * BUFO);
}

__global__ __launch_bounds__(512, 2) void w2_partial_kernel(
        const float* __restrict__ A, const float* __restrict__ W,
        float* __restrict__ P) {
    extern __shared__ uint32_t smg[];
    int z = blockIdx.z;
    const int KC = FFq / SPLITK;     // 1536
    gemm_body<false, false, false>(A + z * KC, W + z * KC, nullptr, nullptr,
                                   P + (size_t)z * Mq * Dq, Dq, KC, FFq,
                                   blockIdx.y, blockIdx.x,
                                   smg, smg + STAGES * BUFO);
}

// reduce: out = P[0] + P[1] + b2 + res   (deterministic fixed order)
__global__ __launch_bounds__(256) void w2_reduce_kernel(
        const float* __restrict__ P, const float* __restrict__ b2,
        const float* __restrict__ res, float* __restrict__ out) {
    size_t i4 = ((size_t)blockIdx.x * 256 + threadIdx.x) * 4;
    const size_t STR = (size_t)Mq * Dq;
    float4 v0 = *(const float4*)(P + i4);
    float4 v1 = *(const float4*)(P + STR + i4);
    int col = (int)(i4 % Dq);
    float4 bv = *(const float4*)(b2 + col);
    float4 rv = *(const float4*)(res + i4);
    float4 o;
    o.x = (v0.x + v1.x) + bv.x + rv.x;
    o.y = (v0.y + v1.y) + bv.y + rv.y;
    o.z = (v0.z + v1.z) + bv.z + rv.z;
    o.w = (v0.w + v1.w) + bv.w + rv.w;
    *(float4*)(out + i4) = o;
}

// ---------------- tf32 GEMM B (Wo): CTA 128x64, 256 thr, warp 32x32, 4-stage (R12) ------
#define BUFA64 (128 * GST)     // 10240 B
#define BUFB64 (64 * GST)      // 5120 B
#define G64SMEM_BYTES (STAGES * (BUFA64 + BUFB64) * 4)   // 61440 B

template<bool HAS_RES>
__device__ __forceinline__ void gemm_body64(
        const float* __restrict__ A,
        const float* __restrict__ W,
        const float* __restrict__ res,
        float* __restrict__ C,
        int N, int K, int lda, int bm, int bn,
        uint32_t* As, uint32_t* Bs)
{
    int tid = threadIdx.x;                 // 256
    int warp = tid >> 5, lane = tid & 31;
    int wm = warp >> 1, wn = warp & 1;     // 4 x 2 warp grid
    int gid = lane >> 2, tig = lane & 3;

    int lrA = tid >> 1, selA = (tid & 1) * 8;
    const float* Ap = A + (size_t)(bm * 128 + lrA) * lda + selA;
    uint32_t sA = smem_u32(As) + (uint32_t)(lrA * GST + selA) * 4u;
    int lrB = tid >> 2, selB = (tid & 3) * 4;
    const float* Wp = W + (size_t)(bn * 64 + lrB) * lda + selB;
    uint32_t sB = smem_u32(Bs) + (uint32_t)(lrB * GST + selB) * 4u;

    float c[2][4][4];
    #pragma unroll
    for (int i = 0; i < 2; i++)
        #pragma unroll
        for (int j = 0; j < 4; j++)
            #pragma unroll
            for (int f = 0; f < 4; f++) c[i][j][f] = 0.f;

    const int NT = K / 16;

    #pragma unroll
    for (int s = 0; s < STAGES - 1; s++) {
        if (s < NT) {
            cp_async16(sA + (uint32_t)(s * BUFA64) * 4u,      Ap + s * 16);
            cp_async16(sA + (uint32_t)(s * BUFA64) * 4u + 16, Ap + s * 16 + 4);
            cp_async16(sB + (uint32_t)(s * BUFB64) * 4u,      Wp + s * 16);
        }
        CP_COMMIT();
    }

    for (int t = 0; t < NT; t++) {
        CP_WAIT2();
        __syncthreads();

        int st = t & (STAGES - 1);
        const uint32_t* Ab = As + st * BUFA64;
        const uint32_t* Bb = Bs + st * BUFB64;
        #pragma unroll
        for (int ks = 0; ks < 2; ks++) {
            int kb = ks * 8;
            uint32_t af[2][4], bf[4][2];
            #pragma unroll
            for (int i = 0; i < 2; i++) {
                int row = wm * 32 + i * 16 + gid;
                af[i][0] = Ab[row * GST + kb + tig];
                af[i][1] = Ab[(row + 8) * GST + kb + tig];
                af[i][2] = Ab[row * GST + kb + tig + 4];
                af[i][3] = Ab[(row + 8) * GST + kb + tig + 4];
            }
            #pragma unroll
            for (int j = 0; j < 4; j++) {
                int col = wn * 32 + j * 8 + gid;
                bf[j][0] = Bb[col * GST + kb + tig];
                bf[j][1] = Bb[col * GST + kb + tig + 4];
            }
            #pragma unroll
            for (int i = 0; i < 2; i++)
                #pragma unroll
                for (int j = 0; j < 4; j++)
                    mma_tf32(c[i][j], af[i], bf[j]);
        }

        int nt = t + STAGES - 1;
        if (nt < NT) {
            int ns = nt & (STAGES - 1);
            cp_async16(sA + (uint32_t)(ns * BUFA64) * 4u,      Ap + nt * 16);
            cp_async16(sA + (uint32_t)(ns * BUFA64) * 4u + 16, Ap + nt * 16 + 4);
            cp_async16(sB + (uint32_t)(ns * BUFB64) * 4u,      Wp + nt * 16);
        }
        CP_COMMIT();
    }

    #pragma unroll
    for (int i = 0; i < 2; i++) {
        #pragma unroll
        for (int j = 0; j < 4; j++) {
            int row0 = bm * 128 + wm * 32 + i * 16 + gid;
            int col0 = bn * 64 + wn * 32 + j * 8 + 2 * tig;
            #pragma unroll
            for (int half = 0; half < 2; half++) {
                int m = row0 + half * 8;
                float v0 = c[i][j][half * 2 + 0];
                float v1 = c[i][j][half * 2 + 1];
                if (HAS_RES) {
                    float2 r = *(const float2*)(res + (size_t)m * N + col0);
                    v0 += r.x; v1 += r.y;
                }
                *(float2*)(C + (size_t)m * N + col0) = make_float2(v0, v1);
            }
        }
    }
}

__global__ __launch_bounds__(256, 3) void wo_kernel(
        const float* __restrict__ A, const float* __restrict__ W,
        const float* __restrict__ res, float* __restrict__ C) {
    extern __shared__ uint32_t smg[];
    gemm_body64<true>(A, W, res, C, Dq, Dq, Dq,
                      blockIdx.y, blockIdx.x, smg, smg + STAGES * BUFA64);
}

// ---------------- Flash attention on tensor cores (tf32 rna) ----------------
#define ATS 68
#define AT_SMEM_BYTES (4 * 64 * ATS * 4 + 4 * 64 * 4)

__global__ __launch_bounds__(256) void attn_kernel(const float* __restrict__ Q,
                                                   const float* __restrict__ K,
                                                   const float* __restrict__ V,
                                                   float* __restrict__ out) {
    extern __shared__ uint32_t asmem[];
    uint32_t* Qs = asmem;
    uint32_t* Ks = asmem + 64 * ATS;
    uint32_t* VT = asmem + 2 * 64 * ATS;
    uint32_t* Ps = asmem + 3 * 64 * ATS;
    float* red = (float*)(asmem + 4 * 64 * ATS);   // [4][64]

    int bh = blockIdx.y;
    int qt = 15 - blockIdx.x;
    int tid = threadIdx.x;
    int warp = tid >> 5, lane = tid & 31;
    int wm = warp >> 2, wn = warp & 3;     // 2 x 4
    int gid = lane >> 2, tig = lane & 3;

    const float* Qp = Q + (size_t)bh * Sq * HDq;
    const float* Kp = K + (size_t)bh * Sq * HDq;
    const float* Vp = V + (size_t)bh * Sq * HDq;

    for (int t = tid; t < 1024; t += 256) {
        int r = t >> 4, cc = (t & 15) * 4;
        float4 qv = *(const float4*)(Qp + (size_t)(qt * 64 + r) * HDq + cc);
        Qs[r * ATS + cc + 0] = f2tf32(qv.x * 0.015625f);
        Qs[r * ATS + cc + 1] = f2tf32(qv.y * 0.015625f);
        Qs[r * ATS + cc + 2] = f2tf32(qv.z * 0.015625f);
        Qs[r * ATS + cc + 3] = f2tf32(qv.w * 0.015625f);
    }

    float o_[2][2][4];
    float m_i[4], l_i[4];
    #pragma unroll
    for (int r = 0; r < 4; r++) { m_i[r] = -1e30f; l_i[r] = 0.f; }
    #pragma unroll
    for (int i = 0; i < 2; i++)
        #pragma unroll
        for (int j = 0; j < 2; j++)
            #pragma unroll
            for (int e = 0; e < 4; e++) o_[i][j][e] = 0.f;

    for (int kt = 0; kt <= qt; kt++) {
        __syncthreads();
        for (int t = tid; t < 1024; t += 256) {
            int k = t & 63, cc = (t >> 6) * 4;
            float4 kv = *(const float4*)(Kp + (size_t)(kt * 64 + k) * HDq + cc);
            Ks[k * ATS + cc + 0] = f2tf32(kv.x);
            Ks[k * ATS + cc + 1] = f2tf32(kv.y);
            Ks[k * ATS + cc + 2] = f2tf32(kv.z);
            Ks[k * ATS + cc + 3] = f2tf32(kv.w);
            float4 vv = *(const float4*)(Vp + (size_t)(kt * 64 + k) * HDq + cc);
            VT[(cc + 0) * ATS + k] = f2tf32(vv.x);
            VT[(cc + 1) * ATS + k] = f2tf32(vv.y);
            VT[(cc + 2) * ATS + k] = f2tf32(vv.z);
            VT[(cc + 3) * ATS + k] = f2tf32(vv.w);
        }
        __syncthreads();

        float s_[2][2][4];
        #pragma unroll
        for (int i = 0; i < 2; i++)
            #pragma unroll
            for (int j = 0; j < 2; j++)
                #pragma unroll
                for (int e = 0; e < 4; e++) s_[i][j][e] = 0.f;
        #pragma unroll
        for (int kd = 0; kd < 8; kd++) {
            int kb = kd * 8;
            uint32_t af[2][4], bf[2][2];
            #pragma unroll
            for (int i = 0; i < 2; i++) {
                int row = wm * 32 + i * 16 + gid;
                af[i][0] = Qs[row * ATS + kb + tig];
                af[i][1] = Qs[(row + 8) * ATS + kb + tig];
                af[i][2] = Qs[row * ATS + kb + tig + 4];
                af[i][3] = Qs[(row + 8) * ATS + kb + tig + 4];
            }
            #pragma unroll
            for (int j = 0; j < 2; j++) {
                int col = wn * 16 + j * 8 + gid;
                bf[j][0] = Ks[col * ATS + kb + tig];
                bf[j][1] = Ks[col * ATS + kb + tig + 4];
            }
            #pragma unroll
            for (int i = 0; i < 2; i++)
                #pragma unroll
                for (int j = 0; j < 2; j++)
                    mma_tf32(s_[i][j], af[i], bf[j]);
        }

        if (kt == qt) {
            #pragma unroll
            for (int i = 0; i < 2; i++)
                #pragma unroll
                for (int j = 0; j < 2; j++)
                    #pragma unroll
                    for (int e = 0; e < 4; e++) {
                        int row = wm * 32 + i * 16 + ((e >> 1) ? 8 : 0) + gid;
                        int col = wn * 16 + j * 8 + 2 * tig + (e & 1);
                        if (col > row) s_[i][j][e] = -1e30f;
                    }
        }

        #pragma unroll
        for (int r = 0; r < 4; r++) {
            int i = r >> 1, half = r & 1;
            float v = fmaxf(fmaxf(s_[i][0][half * 2], s_[i][0][half * 2 + 1]),
                            fmaxf(s_[i][1][half * 2], s_[i][1][half * 2 + 1]));
            v = fmaxf(v, __shfl_xor_sync(0xffffffff, v, 1));
            v = fmaxf(v, __shfl_xor_sync(0xffffffff, v, 2));
            if (tig == 0)
                red[wn * 64 + wm * 32 + i * 16 + half * 8 + gid] = v;
        }
        __syncthreads();

        float alpha[4];
        #pragma unroll
        for (int r = 0; r < 4; r++) {
            int i = r >> 1, half = r & 1;
            int rowg = wm * 32 + i * 16 + half * 8 + gid;
            float tm = fmaxf(fmaxf(red[rowg], red[64 + rowg]),
                             fmaxf(red[128 + rowg], red[192 + rowg]));
            float Mnew = fmaxf(m_i[r], tm);
            alpha[r] = __expf(m_i[r] - Mnew);
            m_i[r] = Mnew;
            l_i[r] *= alpha[r];
        }

        #pragma unroll
        for (int i = 0; i < 2; i++)
            #pragma unroll
            for (int half = 0; half < 2; half++) {
                int r = i * 2 + half;
                int row = wm * 32 + i * 16 + half * 8 + gid;
                #pragma unroll
                for (int j = 0; j < 2; j++) {
                    #pragma unroll
                    for (int e2 = 0; e2 < 2; e2++) {
                        int e = half * 2 + e2;
                        o_[i][j][e] *= alpha[r];
                        float p = __expf(s_[i][j][e] - m_i[r]);
                        l_i[r] += p;
                        int col = wn * 16 + j * 8 + 2 * tig + e2;
                        Ps[row * ATS + col] = f2tf32(p);
                    }
                }
            }
        __syncthreads();

        #pragma unroll
        for (int kk = 0; kk < 8; kk++) {
            int kb = kk * 8;
            uint32_t af[2][4], bf[2][2];
            #pragma unroll
            for (int i = 0; i < 2; i++) {
                int row = wm * 32 + i * 16 + gid;
                af[i][0] = Ps[row * ATS + kb + tig];
                af[i][1] = Ps[(row + 8) * ATS + kb + tig];
                af[i][2] = Ps[row * ATS + kb + tig + 4];
                af[i][3] = Ps[(row + 8) * ATS + kb + tig + 4];
            }
            #pragma unroll
            for (int j = 0; j < 2; j++) {
                int col = wn * 16 + j * 8 + gid;
                bf[j][0] = VT[col * ATS + kb + tig];
                bf[j][1] = VT[col * ATS + kb + tig + 4];
            }
            #pragma unroll
            for (int i = 0; i < 2; i++)
                #pragma unroll
                for (int j = 0; j < 2; j++)
                    mma_tf32(o_[i][j], af[i], bf[j]);
        }
    }

    #pragma unroll
    for (int r = 0; r < 4; r++) {
        float v = l_i[r];
        v += __shfl_xor_sync(0xffffffff, v, 1);
        v += __shfl_xor_sync(0xffffffff, v, 2);
        l_i[r] = v;
    }
    __syncthreads();
    if (tig == 0) {
        #pragma unroll
        for (int r = 0; r < 4; r++)
            red[wn * 64 + wm * 32 + (r >> 1) * 16 + (r & 1) * 8 + gid] = l_i[r];
    }
    __syncthreads();

    int b = bh / Hq, h = bh % Hq;
    #pragma unroll
    for (int i = 0; i < 2; i++)
        #pragma unroll
        for (int half = 0; half < 2; half++) {
            int rowg = wm * 32 + i * 16 + half * 8 + gid;
            float lt = ((red[rowg] + red[64 + rowg]) + (red[128 + rowg] + red[192 + rowg]));
            float inv = 1.0f / lt;
            int qrow = qt * 64 + rowg;
            #pragma unroll
            for (int j = 0; j < 2; j++) {
                int col = h * HDq + wn * 16 + j * 8 + 2 * tig;
                float v0 = o_[i][j][half * 2 + 0] * inv;
                float v1 = o_[i][j][half * 2 + 1] * inv;
                *(float2*)(out + ((size_t)(b * Sq + qrow)) * Dq + col) = make_float2(v0, v1);
            }
        }
}

// ---------------- launch ----------------
extern "C" void kernel_launch(void* const* d_in, const int* in_sizes, int n_in,
                              void* d_out, int out_size) {
    const float* x  = (const float*)d_in[0];
    const float* Wq = (const float*)d_in[1];
    const float* Wk = (const float*)d_in[2];
    const float* Wv = (const float*)d_in[3];
    const float* Wo = (const float*)d_in[4];
    const float* W1 = (const float*)d_in[5];
    const float* b1 = (const float*)d_in[6];
    const float* W2 = (const float*)d_in[7];
    const float* b2 = (const float*)d_in[8];
    const float* g1 = (const float*)d_in[9];
    const float* s1 = (const float*)d_in[10];
    const float* g2 = (const float*)d_in[11];
    const float* s2 = (const float*)d_in[12];
    float* out = (float*)d_out;

    float *h, *q, *k, *v, *at, *x2, *ff, *part;
    cudaGetSymbolAddress((void**)&h,  g_h);
    cudaGetSymbolAddress((void**)&q,  g_q);
    cudaGetSymbolAddress((void**)&k,  g_k);
    cudaGetSymbolAddress((void**)&v,  g_v);
    cudaGetSymbolAddress((void**)&at, g_at);
    cudaGetSymbolAddress((void**)&x2, g_x2);
    cudaGetSymbolAddress((void**)&ff, g_ff);
    cudaGetSymbolAddress((void**)&part, g_part);

    static bool attr_set = false;
    if (!attr_set) {
        cudaFuncSetAttribute(attn_kernel,
                             cudaFuncAttributeMaxDynamicSharedMemorySize, AT_SMEM_BYTES);
        cudaFuncSetAttribute(tgemm_kernel<true, true, false>,
                             cudaFuncAttributeMaxDynamicSharedMemorySize, GSMEM_BYTES);
        cudaFuncSetAttribute(qkv_kernel,
                             cudaFuncAttributeMaxDynamicSharedMemorySize, GSMEM_BYTES);
        cudaFuncSetAttribute(w2_partial_kernel,
                             cudaFuncAttributeMaxDynamicSharedMemorySize, GSMEM_BYTES);
        cudaFuncSetAttribute(wo_kernel,
                             cudaFuncAttributeMaxDynamicSharedMemorySize, G64SMEM_BYTES);
        attr_set = true;
    }

    dim3 gQKV(Dq / 128, Mq / 128, 3);    // (6, 32, 3)
    dim3 gWO(Dq / 64, Mq / 128);         // (12, 32) = 384 CTAs @3/SM
    dim3 gDF(FFq / 128, Mq / 128);       // (24, 32)
    dim3 gW2(Dq / 128, Mq / 128, SPLITK);// (6, 32, 2)

    // LN1
    ln_kernel<<<Mq, 256>>>(x, g1, s1, h);
    // fused Q,K,V projections
    qkv_kernel<<<gQKV, 512, GSMEM_BYTES>>>(h, Wq, Wk, Wv, q, k, v);
    // flash attention (tensor cores)
    {
        dim3 ga(16, Bq * Hq);
        attn_kernel<<<ga, 256, AT_SMEM_BYTES>>>(q, k, v, at);
    }
    // output projection + residual (128x64-tile body, better wave packing)
    wo_kernel<<<gWO, 256, G64SMEM_BYTES>>>(at, Wo, x, x2);
    // LN2
    ln_kernel<<<Mq, 256>>>(x2, g2, s2, h);
    // MLP up + GELU
    tgemm_kernel<true, true, false><<<gDF, 512, GSMEM_BYTES>>>(h, W1, b1, nullptr, ff, FFq, Dq, Dq);
    // MLP down: split-K=2 partials + deterministic reduce
    w2_partial_kernel<<<gW2, 512, GSMEM_BYTES>>>(ff, W2, part);
    w2_reduce_kernel<<<(Mq * Dq) / (256 * 4), 256>>>(part, b2, x2, out);
}

// round 17
// speedup vs baseline: 1.0759x; 1.0165x over previous
#include <cuda_runtime.h>
#include <cuda_bf16.h>
#include <math.h>
#include <stdint.h>

#define Bq 4
#define Sq 1024
#define Dq 768
#define Hq 12
#define HDq 64
#define FFq 3072
#define Mq (Bq*Sq)   // 4096
#define EPSq 1e-5f
#define SPLITK 2

// ---------------- scratch (static device globals; no allocation) ----------------
__device__ float g_h [Mq*Dq];
__device__ float g_q [Mq*Dq];
__device__ float g_k [Mq*Dq];
__device__ float g_v [Mq*Dq];
__device__ float g_at[Mq*Dq];
__device__ float g_x2[Mq*Dq];
__device__ float g_ff[Mq*FFq];
__device__ float g_part[SPLITK * Mq * Dq];

// ---------------- LayerNorm ----------------
__global__ void ln_kernel(const float* __restrict__ x,
                          const float* __restrict__ g,
                          const float* __restrict__ s,
                          float* __restrict__ out) {
    int row = blockIdx.x;
    int t = threadIdx.x;
    const float* xr = x + (size_t)row * Dq;
    float v0 = xr[t], v1 = xr[t + 256], v2 = xr[t + 512];
    float lsum = v0 + v1 + v2;
    float lsq  = v0*v0 + v1*v1 + v2*v2;

    __shared__ float rs[64], rq[64];
    for (int o = 16; o > 0; o >>= 1) {
        lsum += __shfl_down_sync(0xffffffff, lsum, o);
        lsq  += __shfl_down_sync(0xffffffff, lsq,  o);
    }
    int warp = t >> 5, lane = t & 31;
    if (lane == 0) { rs[warp] = lsum; rq[warp] = lsq; }
    __syncthreads();
    if (warp == 0) {
        float a = (lane < 8) ? rs[lane] : 0.f;
        float b = (lane < 8) ? rq[lane] : 0.f;
        for (int o = 4; o > 0; o >>= 1) {
            a += __shfl_down_sync(0xffffffff, a, o);
            b += __shfl_down_sync(0xffffffff, b, o);
        }
        if (lane == 0) { rs[0] = a; rq[0] = b; }
    }
    __syncthreads();
    float mean = rs[0] * (1.0f / Dq);
    float var  = rq[0] * (1.0f / Dq) - mean * mean;
    float inv  = rsqrtf(var + EPSq);
    float* orow = out + (size_t)row * Dq;
    orow[t]       = (v0 - mean) * inv * g[t]       + s[t];
    orow[t + 256] = (v1 - mean) * inv * g[t + 256] + s[t + 256];
    orow[t + 512] = (v2 - mean) * inv * g[t + 512] + s[t + 512];
}

// ---------------- shared PTX helpers ----------------
__device__ __forceinline__ uint32_t smem_u32(const void* p) {
    uint32_t a;
    asm("{ .reg .u64 t; cvta.to.shared.u64 t, %1; cvt.u32.u64 %0, t; }" : "=r"(a) : "l"(p));
    return a;
}
__device__ __forceinline__ void cp_async16(uint32_t saddr, const void* gptr) {
    asm volatile("cp.async.cg.shared.global [%0], [%1], 16;" :: "r"(saddr), "l"(gptr));
}
#define CP_COMMIT() asm volatile("cp.async.commit_group;" ::: "memory")
#define CP_WAIT2()  asm volatile("cp.async.wait_group 2;" ::: "memory")

__device__ __forceinline__ uint32_t f2tf32(float x) {
    uint32_t r;
    asm("cvt.rna.tf32.f32 %0, %1;" : "=r"(r) : "f"(x));
    return r;
}
__device__ __forceinline__ void mma_tf32(float c[4], const uint32_t a[4], const uint32_t b[2]) {
    asm("mma.sync.aligned.m16n8k8.row.col.f32.tf32.tf32.f32 "
        "{%0,%1,%2,%3}, {%4,%5,%6,%7}, {%8,%9}, {%0,%1,%2,%3};"
        : "+f"(c[0]), "+f"(c[1]), "+f"(c[2]), "+f"(c[3])
        : "r"(a[0]), "r"(a[1]), "r"(a[2]), "r"(a[3]), "r"(b[0]), "r"(b[1]));
}

// ---------------- tf32 GEMM A: CTA 128x128, 512 threads, warp 32x32, 4-stage ------
#define GST 20
#define STAGES 4
#define BUFO (128 * GST)
#define GSMEM_BYTES (STAGES * BUFO * 4 * 2)     // 81920 B

template<bool HAS_BIAS, bool DO_GELU, bool HAS_RES>
__device__ __forceinline__ void gemm_body(
        const float* __restrict__ A,
        const float* __restrict__ W,
        const float* __restrict__ bias,
        const float* __restrict__ res,
        float* __restrict__ C,
        int N, int K, int lda, int bm, int bn,
        uint32_t* As, uint32_t* Bs)
{
    int tid = threadIdx.x;                 // 512
    int warp = tid >> 5, lane = tid & 31;
    int wm = warp >> 2, wn = warp & 3;
    int gid = lane >> 2, tig = lane & 3;

    int lr = tid >> 2, sel = (tid & 3) * 4;
    const float* Ap = A + (size_t)(bm * 128 + lr) * lda + sel;
    const float* Wp = W + (size_t)(bn * 128 + lr) * lda + sel;
    uint32_t sA = smem_u32(As) + (uint32_t)(lr * GST + sel) * 4u;
    uint32_t sB = smem_u32(Bs) + (uint32_t)(lr * GST + sel) * 4u;

    float c[2][4][4];
    #pragma unroll
    for (int i = 0; i < 2; i++)
        #pragma unroll
        for (int j = 0; j < 4; j++)
            #pragma unroll
            for (int f = 0; f < 4; f++) c[i][j][f] = 0.f;

    const int NT = K / 16;

    #pragma unroll
    for (int s = 0; s < STAGES - 1; s++) {
        if (s < NT) {
            cp_async16(sA + (uint32_t)(s * BUFO) * 4u, Ap + s * 16);
            cp_async16(sB + (uint32_t)(s * BUFO) * 4u, Wp + s * 16);
        }
        CP_COMMIT();
    }

    for (int t = 0; t < NT; t++) {
        CP_WAIT2();
        __syncthreads();

        int st = t & (STAGES - 1);
        const uint32_t* Ab = As + st * BUFO;
        const uint32_t* Bb = Bs + st * BUFO;
        #pragma unroll
        for (int ks = 0; ks < 2; ks++) {
            int kb = ks * 8;
            uint32_t af[2][4], bf[4][2];
            #pragma unroll
            for (int i = 0; i < 2; i++) {
                int row = wm * 32 + i * 16 + gid;
                af[i][0] = Ab[row * GST + kb + tig];
                af[i][1] = Ab[(row + 8) * GST + kb + tig];
                af[i][2] = Ab[row * GST + kb + tig + 4];
                af[i][3] = Ab[(row + 8) * GST + kb + tig + 4];
            }
            #pragma unroll
            for (int j = 0; j < 4; j++) {
                int col = wn * 32 + j * 8 + gid;
                bf[j][0] = Bb[col * GST + kb + tig];
                bf[j][1] = Bb[col * GST + kb + tig + 4];
            }
            #pragma unroll
            for (int i = 0; i < 2; i++)
                #pragma unroll
                for (int j = 0; j < 4; j++)
                    mma_tf32(c[i][j], af[i], bf[j]);
        }

        int nt = t + STAGES - 1;
        if (nt < NT) {
            int ns = nt & (STAGES - 1);
            cp_async16(sA + (uint32_t)(ns * BUFO) * 4u, Ap + nt * 16);
            cp_async16(sB + (uint32_t)(ns * BUFO) * 4u, Wp + nt * 16);
        }
        CP_COMMIT();
    }

    #pragma unroll
    for (int i = 0; i < 2; i++) {
        #pragma unroll
        for (int j = 0; j < 4; j++) {
            int row0 = bm * 128 + wm * 32 + i * 16 + gid;
            int col0 = bn * 128 + wn * 32 + j * 8 + 2 * tig;
            #pragma unroll
            for (int half = 0; half < 2; half++) {
                int m = row0 + half * 8;
                float v0 = c[i][j][half * 2 + 0];
                float v1 = c[i][j][half * 2 + 1];
                if (HAS_BIAS) { v0 += bias[col0]; v1 += bias[col0 + 1]; }
                if (DO_GELU) {
                    float x3 = v0 * v0 * v0;
                    float tt = tanhf(0.7978845608028654f * (v0 + 0.044715f * x3));
                    v0 = 0.5f * v0 * (1.0f + tt);
                    x3 = v1 * v1 * v1;
                    tt = tanhf(0.7978845608028654f * (v1 + 0.044715f * x3));
                    v1 = 0.5f * v1 * (1.0f + tt);
                }
                if (HAS_RES) {
                    float2 r = *(const float2*)(res + (size_t)m * N + col0);
                    v0 += r.x; v1 += r.y;
                }
                *(float2*)(C + (size_t)m * N + col0) = make_float2(v0, v1);
            }
        }
    }
}

template<bool HAS_BIAS, bool DO_GELU, bool HAS_RES>
__global__ __launch_bounds__(512, 2) void tgemm_kernel(
        const float* __restrict__ A, const float* __restrict__ W,
        const float* __restrict__ bias, const float* __restrict__ res,
        float* __restrict__ C, int N, int K, int lda) {
    extern __shared__ uint32_t smg[];
    gemm_body<HAS_BIAS, DO_GELU, HAS_RES>(A, W, bias, res, C, N, K, lda,
                                          blockIdx.y, blockIdx.x,
                                          smg, smg + STAGES * BUFO);
}

__global__ __launch_bounds__(512, 2) void qkv_kernel(
        const float* __restrict__ A,
        const float* __restrict__ Wqp, const float* __restrict__ Wkp, const float* __restrict__ Wvp,
        float* __restrict__ Qo, float* __restrict__ Ko, float* __restrict__ Vo) {
    extern __shared__ uint32_t smg[];
    const float* W = (blockIdx.z == 0) ? Wqp : (blockIdx.z == 1) ? Wkp : Wvp;
    float* C = (blockIdx.z == 0) ? Qo : (blockIdx.z == 1) ? Ko : Vo;
    gemm_body<false, false, false>(A, W, nullptr, nullptr, C, Dq, Dq, Dq,
                                   blockIdx.y, blockIdx.x,
                                   smg, smg + STAGES * BUFO);
}

__global__ __launch_bounds__(512, 2) void w2_partial_kernel(
        const float* __restrict__ A, const float* __restrict__ W,
        float* __restrict__ P) {
    extern __shared__ uint32_t smg[];
    int z = blockIdx.z;
    const int KC = FFq / SPLITK;     // 1536
    gemm_body<false, false, false>(A + z * KC, W + z * KC, nullptr, nullptr,
                                   P + (size_t)z * Mq * Dq, Dq, KC, FFq,
                                   blockIdx.y, blockIdx.x,
                                   smg, smg + STAGES * BUFO);
}

__global__ __launch_bounds__(256) void w2_reduce_kernel(
        const float* __restrict__ P, const float* __restrict__ b2,
        const float* __restrict__ res, float* __restrict__ out) {
    size_t i4 = ((size_t)blockIdx.x * 256 + threadIdx.x) * 4;
    const size_t STR = (size_t)Mq * Dq;
    float4 v0 = *(const float4*)(P + i4);
    float4 v1 = *(const float4*)(P + STR + i4);
    int col = (int)(i4 % Dq);
    float4 bv = *(const float4*)(b2 + col);
    float4 rv = *(const float4*)(res + i4);
    float4 o;
    o.x = (v0.x + v1.x) + bv.x + rv.x;
    o.y = (v0.y + v1.y) + bv.y + rv.y;
    o.z = (v0.z + v1.z) + bv.z + rv.z;
    o.w = (v0.w + v1.w) + bv.w + rv.w;
    *(float4*)(out + i4) = o;
}

// ---------------- tf32 GEMM B (Wo): CTA 128x64, 256 thr, 4-stage ------
#define BUFA64 (128 * GST)
#define BUFB64 (64 * GST)
#define G64SMEM_BYTES (STAGES * (BUFA64 + BUFB64) * 4)   // 61440 B

template<bool HAS_RES>
__device__ __forceinline__ void gemm_body64(
        const float* __restrict__ A,
        const float* __restrict__ W,
        const float* __restrict__ res,
        float* __restrict__ C,
        int N, int K, int lda, int bm, int bn,
        uint32_t* As, uint32_t* Bs)
{
    int tid = threadIdx.x;                 // 256
    int warp = tid >> 5, lane = tid & 31;
    int wm = warp >> 1, wn = warp & 1;
    int gid = lane >> 2, tig = lane & 3;

    int lrA = tid >> 1, selA = (tid & 1) * 8;
    const float* Ap = A + (size_t)(bm * 128 + lrA) * lda + selA;
    uint32_t sA = smem_u32(As) + (uint32_t)(lrA * GST + selA) * 4u;
    int lrB = tid >> 2, selB = (tid & 3) * 4;
    const float* Wp = W + (size_t)(bn * 64 + lrB) * lda + selB;
    uint32_t sB = smem_u32(Bs) + (uint32_t)(lrB * GST + selB) * 4u;

    float c[2][4][4];
    #pragma unroll
    for (int i = 0; i < 2; i++)
        #pragma unroll
        for (int j = 0; j < 4; j++)
            #pragma unroll
            for (int f = 0; f < 4; f++) c[i][j][f] = 0.f;

    const int NT = K / 16;

    #pragma unroll
    for (int s = 0; s < STAGES - 1; s++) {
        if (s < NT) {
            cp_async16(sA + (uint32_t)(s * BUFA64) * 4u,      Ap + s * 16);
            cp_async16(sA + (uint32_t)(s * BUFA64) * 4u + 16, Ap + s * 16 + 4);
            cp_async16(sB + (uint32_t)(s * BUFB64) * 4u,      Wp + s * 16);
        }
        CP_COMMIT();
    }

    for (int t = 0; t < NT; t++) {
        CP_WAIT2();
        __syncthreads();

        int st = t & (STAGES - 1);
        const uint32_t* Ab = As + st * BUFA64;
        const uint32_t* Bb = Bs + st * BUFB64;
        #pragma unroll
        for (int ks = 0; ks < 2; ks++) {
            int kb = ks * 8;
            uint32_t af[2][4], bf[4][2];
            #pragma unroll
            for (int i = 0; i < 2; i++) {
                int row = wm * 32 + i * 16 + gid;
                af[i][0] = Ab[row * GST + kb + tig];
                af[i][1] = Ab[(row + 8) * GST + kb + tig];
                af[i][2] = Ab[row * GST + kb + tig + 4];
                af[i][3] = Ab[(row + 8) * GST + kb + tig + 4];
            }
            #pragma unroll
            for (int j = 0; j < 4; j++) {
                int col = wn * 32 + j * 8 + gid;
                bf[j][0] = Bb[col * GST + kb + tig];
                bf[j][1] = Bb[col * GST + kb + tig + 4];
            }
            #pragma unroll
            for (int i = 0; i < 2; i++)
                #pragma unroll
                for (int j = 0; j < 4; j++)
                    mma_tf32(c[i][j], af[i], bf[j]);
        }

        int nt = t + STAGES - 1;
        if (nt < NT) {
            int ns = nt & (STAGES - 1);
            cp_async16(sA + (uint32_t)(ns * BUFA64) * 4u,      Ap + nt * 16);
            cp_async16(sA + (uint32_t)(ns * BUFA64) * 4u + 16, Ap + nt * 16 + 4);
            cp_async16(sB + (uint32_t)(ns * BUFB64) * 4u,      Wp + nt * 16);
        }
        CP_COMMIT();
    }

    #pragma unroll
    for (int i = 0; i < 2; i++) {
        #pragma unroll
        for (int j = 0; j < 4; j++) {
            int row0 = bm * 128 + wm * 32 + i * 16 + gid;
            int col0 = bn * 64 + wn * 32 + j * 8 + 2 * tig;
            #pragma unroll
            for (int half = 0; half < 2; half++) {
                int m = row0 + half * 8;
                float v0 = c[i][j][half * 2 + 0];
                float v1 = c[i][j][half * 2 + 1];
                if (HAS_RES) {
                    float2 r = *(const float2*)(res + (size_t)m * N + col0);
                    v0 += r.x; v1 += r.y;
                }
                *(float2*)(C + (size_t)m * N + col0) = make_float2(v0, v1);
            }
        }
    }
}

__global__ __launch_bounds__(256, 3) void wo_kernel(
        const float* __restrict__ A, const float* __restrict__ W,
        const float* __restrict__ res, float* __restrict__ C) {
    extern __shared__ uint32_t smg[];
    gemm_body64<true>(A, W, res, C, Dq, Dq, Dq,
                      blockIdx.y, blockIdx.x, smg, smg + STAGES * BUFA64);
}

// ---------------- Flash attention on tensor cores: 128-q tile, 512 thr ----------------
// Smem: Qs[128], Ks[64], VT[64], Ps[128] rows x ATS tf32 words + red[4][128].
#define ATS 68
#define AT_SMEM_BYTES ((128 + 64 + 64 + 128) * ATS * 4 + 4 * 128 * 4)

__global__ __launch_bounds__(512, 2) void attn_kernel(const float* __restrict__ Q,
                                                      const float* __restrict__ K,
                                                      const float* __restrict__ V,
                                                      float* __restrict__ out) {
    extern __shared__ uint32_t asmem[];
    uint32_t* Qs = asmem;                      // [128][ATS]
    uint32_t* Ks = asmem + 128 * ATS;          // [64][ATS]
    uint32_t* VT = asmem + (128 + 64) * ATS;   // [64][ATS]
    uint32_t* Ps = asmem + (128 + 128) * ATS;  // [128][ATS]
    float* red = (float*)(asmem + (128 + 64 + 64 + 128) * ATS);   // [4][128]

    int bh = blockIdx.y;
    int qt = 7 - blockIdx.x;                   // 128-row q tiles, heavy first
    int tid = threadIdx.x;                     // 512
    int warp = tid >> 5, lane = tid & 31;
    int wm = warp >> 2, wn = warp & 3;         // 4 x 4
    int gid = lane >> 2, tig = lane & 3;

    const float* Qp = Q + (size_t)bh * Sq * HDq;
    const float* Kp = K + (size_t)bh * Sq * HDq;
    const float* Vp = V + (size_t)bh * Sq * HDq;

    // load Q tile (128 rows), scaled 1/64, rna tf32
    for (int t = tid; t < 2048; t += 512) {
        int r = t >> 4, cc = (t & 15) * 4;
        float4 qv = *(const float4*)(Qp + (size_t)(qt * 128 + r) * HDq + cc);
        Qs[r * ATS + cc + 0] = f2tf32(qv.x * 0.015625f);
        Qs[r * ATS + cc + 1] = f2tf32(qv.y * 0.015625f);
        Qs[r * ATS + cc + 2] = f2tf32(qv.z * 0.015625f);
        Qs[r * ATS + cc + 3] = f2tf32(qv.w * 0.015625f);
    }

    float o_[2][2][4];
    float m_i[4], l_i[4];
    #pragma unroll
    for (int r = 0; r < 4; r++) { m_i[r] = -1e30f; l_i[r] = 0.f; }
    #pragma unroll
    for (int i = 0; i < 2; i++)
        #pragma unroll
        for (int j = 0; j < 2; j++)
            #pragma unroll
            for (int e = 0; e < 4; e++) o_[i][j][e] = 0.f;

    int ktmax = 2 * qt + 1;   // k tiles of 64 covering q rows [128qt, 128qt+128)
    for (int kt = 0; kt <= ktmax; kt++) {
        __syncthreads();
        for (int t = tid; t < 1024; t += 512) {
            int k = t & 63, cc = (t >> 6) * 4;
            float4 kv = *(const float4*)(Kp + (size_t)(kt * 64 + k) * HDq + cc);
            Ks[k * ATS + cc + 0] = f2tf32(kv.x);
            Ks[k * ATS + cc + 1] = f2tf32(kv.y);
            Ks[k * ATS + cc + 2] = f2tf32(kv.z);
            Ks[k * ATS + cc + 3] = f2tf32(kv.w);
            float4 vv = *(const float4*)(Vp + (size_t)(kt * 64 + k) * HDq + cc);
            VT[(cc + 0) * ATS + k] = f2tf32(vv.x);
            VT[(cc + 1) * ATS + k] = f2tf32(vv.y);
            VT[(cc + 2) * ATS + k] = f2tf32(vv.z);
            VT[(cc + 3) * ATS + k] = f2tf32(vv.w);
        }
        __syncthreads();

        float s_[2][2][4];
        #pragma unroll
        for (int i = 0; i < 2; i++)
            #pragma unroll
            for (int j = 0; j < 2; j++)
                #pragma unroll
                for (int e = 0; e < 4; e++) s_[i][j][e] = 0.f;
        #pragma unroll
        for (int kd = 0; kd < 8; kd++) {
            int kb = kd * 8;
            uint32_t af[2][4], bf[2][2];
            #pragma unroll
            for (int i = 0; i < 2; i++) {
                int row = wm * 32 + i * 16 + gid;
                af[i][0] = Qs[row * ATS + kb + tig];
                af[i][1] = Qs[(row + 8) * ATS + kb + tig];
                af[i][2] = Qs[row * ATS + kb + tig + 4];
                af[i][3] = Qs[(row + 8) * ATS + kb + tig + 4];
            }
            #pragma unroll
            for (int j = 0; j < 2; j++) {
                int col = wn * 16 + j * 8 + gid;
                bf[j][0] = Ks[col * ATS + kb + tig];
                bf[j][1] = Ks[col * ATS + kb + tig + 4];
            }
            #pragma unroll
            for (int i = 0; i < 2; i++)
                #pragma unroll
                for (int j = 0; j < 2; j++)
                    mma_tf32(s_[i][j], af[i], bf[j]);
        }

        // causal mask via global indices (only tiles at/past diagonal need it)
        if (kt >= 2 * qt) {
            #pragma unroll
            for (int i = 0; i < 2; i++)
                #pragma unroll
                for (int j = 0; j < 2; j++)
                    #pragma unroll
                    for (int e = 0; e < 4; e++) {
                        int rowg = qt * 128 + wm * 32 + i * 16 + ((e >> 1) ? 8 : 0) + gid;
                        int colg = kt * 64 + wn * 16 + j * 8 + 2 * tig + (e & 1);
                        if (colg > rowg) s_[i][j][e] = -1e30f;
                    }
        }

        #pragma unroll
        for (int r = 0; r < 4; r++) {
            int i = r >> 1, half = r & 1;
            float v = fmaxf(fmaxf(s_[i][0][half * 2], s_[i][0][half * 2 + 1]),
                            fmaxf(s_[i][1][half * 2], s_[i][1][half * 2 + 1]));
            v = fmaxf(v, __shfl_xor_sync(0xffffffff, v, 1));
            v = fmaxf(v, __shfl_xor_sync(0xffffffff, v, 2));
            if (tig == 0)
                red[wn * 128 + wm * 32 + i * 16 + half * 8 + gid] = v;
        }
        __syncthreads();

        float alpha[4];
        #pragma unroll
        for (int r = 0; r < 4; r++) {
            int i = r >> 1, half = r & 1;
            int rowl = wm * 32 + i * 16 + half * 8 + gid;
            float tm = fmaxf(fmaxf(red[rowl], red[128 + rowl]),
                             fmaxf(red[256 + rowl], red[384 + rowl]));
            float Mnew = fmaxf(m_i[r], tm);
            alpha[r] = __expf(m_i[r] - Mnew);
            m_i[r] = Mnew;
            l_i[r] *= alpha[r];
        }

        #pragma unroll
        for (int i = 0; i < 2; i++)
            #pragma unroll
            for (int half = 0; half < 2; half++) {
                int r = i * 2 + half;
                int row = wm * 32 + i * 16 + half * 8 + gid;
                #pragma unroll
                for (int j = 0; j < 2; j++) {
                    #pragma unroll
                    for (int e2 = 0; e2 < 2; e2++) {
                        int e = half * 2 + e2;
                        o_[i][j][e] *= alpha[r];
                        float p = __expf(s_[i][j][e] - m_i[r]);
                        l_i[r] += p;
                        int col = wn * 16 + j * 8 + 2 * tig + e2;
                        Ps[row * ATS + col] = f2tf32(p);
                    }
                }
            }
        __syncthreads();

        #pragma unroll
        for (int kk = 0; kk < 8; kk++) {
            int kb = kk * 8;
            uint32_t af[2][4], bf[2][2];
            #pragma unroll
            for (int i = 0; i < 2; i++) {
                int row = wm * 32 + i * 16 + gid;
                af[i][0] = Ps[row * ATS + kb + tig];
                af[i][1] = Ps[(row + 8) * ATS + kb + tig];
                af[i][2] = Ps[row * ATS + kb + tig + 4];
                af[i][3] = Ps[(row + 8) * ATS + kb + tig + 4];
            }
            #pragma unroll
            for (int j = 0; j < 2; j++) {
                int col = wn * 16 + j * 8 + gid;
                bf[j][0] = VT[col * ATS + kb + tig];
                bf[j][1] = VT[col * ATS + kb + tig + 4];
            }
            #pragma unroll
            for (int i = 0; i < 2; i++)
                #pragma unroll
                for (int j = 0; j < 2; j++)
                    mma_tf32(o_[i][j], af[i], bf[j]);
        }
    }

    #pragma unroll
    for (int r = 0; r < 4; r++) {
        float v = l_i[r];
        v += __shfl_xor_sync(0xffffffff, v, 1);
        v += __shfl_xor_sync(0xffffffff, v, 2);
        l_i[r] = v;
    }
    __syncthreads();
    if (tig == 0) {
        #pragma unroll
        for (int r = 0; r < 4; r++)
            red[wn * 128 + wm * 32 + (r >> 1) * 16 + (r & 1) * 8 + gid] = l_i[r];
    }
    __syncthreads();

    int b = bh / Hq, h = bh % Hq;
    #pragma unroll
    for (int i = 0; i < 2; i++)
        #pragma unroll
        for (int half = 0; half < 2; half++) {
            int rowl = wm * 32 + i * 16 + half * 8 + gid;
            float lt = ((red[rowl] + red[128 + rowl]) + (red[256 + rowl] + red[384 + rowl]));
            float inv = 1.0f / lt;
            int qrow = qt * 128 + rowl;
            #pragma unroll
            for (int j = 0; j < 2; j++) {
                int col = h * HDq + wn * 16 + j * 8 + 2 * tig;
                float v0 = o_[i][j][half * 2 + 0] * inv;
                float v1 = o_[i][j][half * 2 + 1] * inv;
                *(float2*)(out + ((size_t)(b * Sq + qrow)) * Dq + col) = make_float2(v0, v1);
            }
        }
}

// ---------------- launch ----------------
extern "C" void kernel_launch(void* const* d_in, const int* in_sizes, int n_in,
                              void* d_out, int out_size) {
    const float* x  = (const float*)d_in[0];
    const float* Wq = (const float*)d_in[1];
    const float* Wk = (const float*)d_in[2];
    const float* Wv = (const float*)d_in[3];
    const float* Wo = (const float*)d_in[4];
    const float* W1 = (const float*)d_in[5];
    const float* b1 = (const float*)d_in[6];
    const float* W2 = (const float*)d_in[7];
    const float* b2 = (const float*)d_in[8];
    const float* g1 = (const float*)d_in[9];
    const float* s1 = (const float*)d_in[10];
    const float* g2 = (const float*)d_in[11];
    const float* s2 = (const float*)d_in[12];
    float* out = (float*)d_out;

    float *h, *q, *k, *v, *at, *x2, *ff, *part;
    cudaGetSymbolAddress((void**)&h,  g_h);
    cudaGetSymbolAddress((void**)&q,  g_q);
    cudaGetSymbolAddress((void**)&k,  g_k);
    cudaGetSymbolAddress((void**)&v,  g_v);
    cudaGetSymbolAddress((void**)&at, g_at);
    cudaGetSymbolAddress((void**)&x2, g_x2);
    cudaGetSymbolAddress((void**)&ff, g_ff);
    cudaGetSymbolAddress((void**)&part, g_part);

    static bool attr_set = false;
    if (!attr_set) {
        cudaFuncSetAttribute(attn_kernel,
                             cudaFuncAttributeMaxDynamicSharedMemorySize, AT_SMEM_BYTES);
        cudaFuncSetAttribute(tgemm_kernel<true, true, false>,
                             cudaFuncAttributeMaxDynamicSharedMemorySize, GSMEM_BYTES);
        cudaFuncSetAttribute(qkv_kernel,
                             cudaFuncAttributeMaxDynamicSharedMemorySize, GSMEM_BYTES);
        cudaFuncSetAttribute(w2_partial_kernel,
                             cudaFuncAttributeMaxDynamicSharedMemorySize, GSMEM_BYTES);
        cudaFuncSetAttribute(wo_kernel,
                             cudaFuncAttributeMaxDynamicSharedMemorySize, G64SMEM_BYTES);
        attr_set = true;
    }

    dim3 gQKV(Dq / 128, Mq / 128, 3);    // (6, 32, 3)
    dim3 gWO(Dq / 64, Mq / 128);         // (12, 32)
    dim3 gDF(FFq / 128, Mq / 128);       // (24, 32)
    dim3 gW2(Dq / 128, Mq / 128, SPLITK);// (6, 32, 2)

    // LN1
    ln_kernel<<<Mq, 256>>>(x, g1, s1, h);
    // fused Q,K,V projections
    qkv_kernel<<<gQKV, 512, GSMEM_BYTES>>>(h, Wq, Wk, Wv, q, k, v);
    // flash attention (tensor cores, 128-row q tiles)
    {
        dim3 ga(8, Bq * Hq);
        attn_kernel<<<ga, 512, AT_SMEM_BYTES>>>(q, k, v, at);
    }
    // output projection + residual
    wo_kernel<<<gWO, 256, G64SMEM_BYTES>>>(at, Wo, x, x2);
    // LN2
    ln_kernel<<<Mq, 256>>>(x2, g2, s2, h);
    // MLP up + GELU
    tgemm_kernel<true, true, false><<<gDF, 512, GSMEM_BYTES>>>(h, W1, b1, nullptr, ff, FFq, Dq, Dq);
    // MLP down: split-K=2 partials + deterministic reduce
    w2_partial_kernel<<<gW2, 512, GSMEM_BYTES>>>(ff, W2, part);
    w2_reduce_kernel<<<(Mq * Dq) / (256 * 4), 256>>>(part, b2, x2, out);
}